// round 1
// baseline (speedup 1.0000x reference)
#include <cuda_runtime.h>
#include <cuda_bf16.h>
#include <math.h>

// Problem constants
#define BB 2
#define TT 2048
#define CC 2048
#define HH 16
#define DD 128
#define MM (BB*TT)          // 4096
#define N_QKV (3*CC)        // 6144

// Scratch (static device globals; no runtime allocation allowed)
__device__ float g_qkv[(size_t)MM * N_QKV];   // [M, 3C]   ~100.7 MB
__device__ float g_q[(size_t)MM * CC];        // [B,H,T,D] ~33.5 MB
__device__ float g_k[(size_t)MM * CC];
__device__ float g_v[(size_t)MM * CC];
__device__ float g_y[(size_t)MM * CC];        // [B,T,C]
__device__ float g_invfreq[DD/2];

// ---------------------------------------------------------------------------
// inv_freq table in double precision (64 threads, one-shot but deterministic)
// ---------------------------------------------------------------------------
__global__ void init_invfreq_kernel() {
    int i = threadIdx.x;
    if (i < DD/2) {
        double e = (double)(2*i) / (double)DD;
        g_invfreq[i] = (float)(1.0 / pow(10000.0, e));
    }
}

// ---------------------------------------------------------------------------
// Classic 128x128x8 register-blocked SGEMM: C[M,N] = A[M,K] * B[K,N]
// A row-major, B row-major. M,N divisible by 128; K divisible by 8.
// 256 threads, each computes an 8x8 micro-tile.
// ---------------------------------------------------------------------------
__global__ __launch_bounds__(256)
void sgemm128_kernel(const float* __restrict__ A,
                     const float* __restrict__ B,
                     float* __restrict__ C,
                     int M, int N, int K)
{
    __shared__ float As[8][128];
    __shared__ float Bs[8][128];

    const int tid = threadIdx.x;
    const int tx = tid & 15;          // 0..15  -> N direction
    const int ty = tid >> 4;          // 0..15  -> M direction
    const int bm = blockIdx.y * 128;
    const int bn = blockIdx.x * 128;

    // Global load assignments
    const int arow = tid >> 1;            // 0..127
    const int acol = (tid & 1) * 4;       // 0 or 4
    const int brow = tid >> 5;            // 0..7
    const int bcol = (tid & 31) * 4;      // 0..124

    const float* Ab = A + (size_t)(bm)*K;
    const float* Bb = B + bn;

    float acc[8][8];
    #pragma unroll
    for (int i = 0; i < 8; i++)
        #pragma unroll
        for (int j = 0; j < 8; j++)
            acc[i][j] = 0.f;

    for (int k0 = 0; k0 < K; k0 += 8) {
        float4 av = *(const float4*)(Ab + (size_t)arow*K + k0 + acol);
        float4 bv = *(const float4*)(Bb + (size_t)(k0 + brow)*N + bcol);
        __syncthreads();
        As[acol+0][arow] = av.x;
        As[acol+1][arow] = av.y;
        As[acol+2][arow] = av.z;
        As[acol+3][arow] = av.w;
        *(float4*)&Bs[brow][bcol] = bv;
        __syncthreads();

        #pragma unroll
        for (int kk = 0; kk < 8; kk++) {
            float4 a0 = *(const float4*)&As[kk][ty*8];
            float4 a1 = *(const float4*)&As[kk][ty*8 + 4];
            float4 b0 = *(const float4*)&Bs[kk][tx*8];
            float4 b1 = *(const float4*)&Bs[kk][tx*8 + 4];
            float af[8] = {a0.x,a0.y,a0.z,a0.w,a1.x,a1.y,a1.z,a1.w};
            float bf[8] = {b0.x,b0.y,b0.z,b0.w,b1.x,b1.y,b1.z,b1.w};
            #pragma unroll
            for (int i = 0; i < 8; i++)
                #pragma unroll
                for (int j = 0; j < 8; j++)
                    acc[i][j] = fmaf(af[i], bf[j], acc[i][j]);
        }
    }

    // Write out (two float4 per row)
    #pragma unroll
    for (int i = 0; i < 8; i++) {
        float* Crow = C + (size_t)(bm + ty*8 + i)*N + bn + tx*8;
        *(float4*)(Crow)     = make_float4(acc[i][0], acc[i][1], acc[i][2], acc[i][3]);
        *(float4*)(Crow + 4) = make_float4(acc[i][4], acc[i][5], acc[i][6], acc[i][7]);
    }
}

// ---------------------------------------------------------------------------
// RoPE + split: read g_qkv [M, 3C], write q/k (roped) and v to [B,H,T,D]
// One thread per (m, c) element, c in [0, C).
// ---------------------------------------------------------------------------
__global__ __launch_bounds__(256)
void rope_split_kernel()
{
    int idx = blockIdx.x * blockDim.x + threadIdx.x;   // over M*C = 8388608
    int m = idx >> 11;         // / 2048
    int c = idx & 2047;
    int t = m & (TT-1);
    int d = c & (DD-1);
    int dm = d & 63;

    float ang = (float)t * g_invfreq[dm];
    float sn, cs;
    sincosf(ang, &sn, &cs);

    size_t base = (size_t)m * N_QKV;
    float qv = g_qkv[base + c];
    float kv = g_qkv[base + CC + c];
    float vv = g_qkv[base + 2*CC + c];

    int c2 = (d < 64) ? (c + 64) : (c - 64);
    float sgn = (d < 64) ? -1.f : 1.f;
    float qr = g_qkv[base + c2];
    float kr = g_qkv[base + CC + c2];

    float qo = qv*cs + sgn*qr*sn;
    float ko = kv*cs + sgn*kr*sn;

    int b = m >> 11;
    int h = c >> 7;
    size_t o = (((size_t)(b*HH + h))*TT + t)*DD + d;
    g_q[o] = qo;
    g_k[o] = ko;
    g_v[o] = vv;
}

// ---------------------------------------------------------------------------
// Causal attention, warp-per-query-row online softmax.
// 8 warps per block, consecutive rows share K/V tiles in L1.
// Output goes directly to [B,T,C] layout in g_y.
// ---------------------------------------------------------------------------
#define AT_WARPS 8
__global__ __launch_bounds__(AT_WARPS*32)
void attn_kernel()
{
    __shared__ float qs[AT_WARPS][DD];

    const int warp = threadIdx.x >> 5;
    const int lane = threadIdx.x & 31;
    const int r = blockIdx.x * AT_WARPS + warp;   // row id in [0, B*H*T)
    const int bh = r >> 11;                        // / T
    const int i  = r & 2047;

    const float* qp = g_q + (size_t)bh*TT*DD + (size_t)i*DD;
    const float* kp = g_k + (size_t)bh*TT*DD;
    const float* vp = g_v + (size_t)bh*TT*DD;

    const float scale = 0.08838834764831845f;   // 1/sqrt(128)
    float4 qv = ((const float4*)qp)[lane];
    qv.x *= scale; qv.y *= scale; qv.z *= scale; qv.w *= scale;
    ((float4*)qs[warp])[lane] = qv;
    __syncwarp();

    const float NEG = -1e30f;
    float mrun = NEG, lrun = 0.f;
    float acc0 = 0.f, acc1 = 0.f, acc2 = 0.f, acc3 = 0.f;

    for (int j0 = 0; j0 <= i; j0 += 32) {
        int jn = min(32, i - j0 + 1);

        float s = NEG;
        if (lane < jn) {
            const float4* krow = (const float4*)(kp + (size_t)(j0 + lane)*DD);
            float dot = 0.f;
            #pragma unroll
            for (int d4 = 0; d4 < DD/4; d4++) {
                float4 kk = krow[d4];
                float4 qq = ((const float4*)qs[warp])[d4];
                dot = fmaf(qq.x, kk.x, dot);
                dot = fmaf(qq.y, kk.y, dot);
                dot = fmaf(qq.z, kk.z, dot);
                dot = fmaf(qq.w, kk.w, dot);
            }
            s = dot;
        }

        // warp max
        float mloc = s;
        #pragma unroll
        for (int off = 16; off; off >>= 1)
            mloc = fmaxf(mloc, __shfl_xor_sync(0xffffffffu, mloc, off));
        float mnew = fmaxf(mrun, mloc);

        float corr = __expf(mrun - mnew);
        float p = (lane < jn) ? __expf(s - mnew) : 0.f;

        float psum = p;
        #pragma unroll
        for (int off = 16; off; off >>= 1)
            psum += __shfl_xor_sync(0xffffffffu, psum, off);

        lrun = lrun * corr + psum;
        acc0 *= corr; acc1 *= corr; acc2 *= corr; acc3 *= corr;

        const float4* vrow = (const float4*)(vp + (size_t)j0*DD);
        #pragma unroll 4
        for (int jj = 0; jj < jn; jj++) {
            float pj = __shfl_sync(0xffffffffu, p, jj);
            float4 vv = vrow[jj*32 + lane];
            acc0 = fmaf(pj, vv.x, acc0);
            acc1 = fmaf(pj, vv.y, acc1);
            acc2 = fmaf(pj, vv.z, acc2);
            acc3 = fmaf(pj, vv.w, acc3);
        }
        mrun = mnew;
    }

    float inv = 1.f / lrun;
    int b = bh >> 4;
    int h = bh & 15;
    float* yp = g_y + ((size_t)(b*TT + i))*CC + h*DD;
    ((float4*)yp)[lane] = make_float4(acc0*inv, acc1*inv, acc2*inv, acc3*inv);
}

// ---------------------------------------------------------------------------
// Launch
// ---------------------------------------------------------------------------
extern "C" void kernel_launch(void* const* d_in, const int* in_sizes, int n_in,
                              void* d_out, int out_size)
{
    const float* x     = (const float*)d_in[0];   // [B,T,C]
    const float* w_qkv = (const float*)d_in[1];   // [C,3C]
    const float* w_out = (const float*)d_in[2];   // [C,C]
    float* out = (float*)d_out;                   // [B,T,C]

    float *qkv_ptr, *y_ptr;
    cudaGetSymbolAddress((void**)&qkv_ptr, g_qkv);
    cudaGetSymbolAddress((void**)&y_ptr,  g_y);

    init_invfreq_kernel<<<1, 64>>>();

    // qkv = x @ w_qkv : [4096, 6144]
    {
        dim3 grid(N_QKV/128, MM/128);
        sgemm128_kernel<<<grid, 256>>>(x, w_qkv, qkv_ptr, MM, N_QKV, CC);
    }

    // RoPE + split into [B,H,T,D]
    rope_split_kernel<<<(MM*CC)/256, 256>>>();

    // causal attention -> g_y [B,T,C]
    attn_kernel<<<(BB*HH*TT)/AT_WARPS, AT_WARPS*32>>>();

    // out = y @ w_out : [4096, 2048]
    {
        dim3 grid(CC/128, MM/128);
        sgemm128_kernel<<<grid, 256>>>(y_ptr, w_out, out, MM, CC, CC);
    }
}

// round 2
// speedup vs baseline: 2.7084x; 2.7084x over previous
#include <cuda_runtime.h>
#include <cuda_bf16.h>
#include <math.h>

// Problem constants
#define BB 2
#define TT 2048
#define CC 2048
#define HH 16
#define DD 128
#define MM (BB*TT)          // 4096
#define N_QKV (3*CC)        // 6144

// Scratch (static device globals; no runtime allocation allowed)
__device__ float g_qkv[(size_t)MM * N_QKV];   // [M, 3C]
__device__ float g_q[(size_t)MM * CC];        // [B,H,T,D]
__device__ float g_k[(size_t)MM * CC];
__device__ float g_v[(size_t)MM * CC];
__device__ float g_y[(size_t)MM * CC];        // [B,T,C]
__device__ float g_invfreq[DD/2];

// ---------------------------------------------------------------------------
__global__ void init_invfreq_kernel() {
    int i = threadIdx.x;
    if (i < DD/2) {
        double e = (double)(2*i) / (double)DD;
        g_invfreq[i] = (float)(1.0 / pow(10000.0, e));
    }
}

// ---------------------------------------------------------------------------
// Classic 128x128x8 register-blocked SGEMM: C[M,N] = A[M,K] * B[K,N]
// ---------------------------------------------------------------------------
__global__ __launch_bounds__(256)
void sgemm128_kernel(const float* __restrict__ A,
                     const float* __restrict__ B,
                     float* __restrict__ C,
                     int M, int N, int K)
{
    __shared__ float As[8][128];
    __shared__ float Bs[8][128];

    const int tid = threadIdx.x;
    const int tx = tid & 15;
    const int ty = tid >> 4;
    const int bm = blockIdx.y * 128;
    const int bn = blockIdx.x * 128;

    const int arow = tid >> 1;
    const int acol = (tid & 1) * 4;
    const int brow = tid >> 5;
    const int bcol = (tid & 31) * 4;

    const float* Ab = A + (size_t)(bm)*K;
    const float* Bb = B + bn;

    float acc[8][8];
    #pragma unroll
    for (int i = 0; i < 8; i++)
        #pragma unroll
        for (int j = 0; j < 8; j++)
            acc[i][j] = 0.f;

    for (int k0 = 0; k0 < K; k0 += 8) {
        float4 av = *(const float4*)(Ab + (size_t)arow*K + k0 + acol);
        float4 bv = *(const float4*)(Bb + (size_t)(k0 + brow)*N + bcol);
        __syncthreads();
        As[acol+0][arow] = av.x;
        As[acol+1][arow] = av.y;
        As[acol+2][arow] = av.z;
        As[acol+3][arow] = av.w;
        *(float4*)&Bs[brow][bcol] = bv;
        __syncthreads();

        #pragma unroll
        for (int kk = 0; kk < 8; kk++) {
            float4 a0 = *(const float4*)&As[kk][ty*8];
            float4 a1 = *(const float4*)&As[kk][ty*8 + 4];
            float4 b0 = *(const float4*)&Bs[kk][tx*8];
            float4 b1 = *(const float4*)&Bs[kk][tx*8 + 4];
            float af[8] = {a0.x,a0.y,a0.z,a0.w,a1.x,a1.y,a1.z,a1.w};
            float bf[8] = {b0.x,b0.y,b0.z,b0.w,b1.x,b1.y,b1.z,b1.w};
            #pragma unroll
            for (int i = 0; i < 8; i++)
                #pragma unroll
                for (int j = 0; j < 8; j++)
                    acc[i][j] = fmaf(af[i], bf[j], acc[i][j]);
        }
    }

    #pragma unroll
    for (int i = 0; i < 8; i++) {
        float* Crow = C + (size_t)(bm + ty*8 + i)*N + bn + tx*8;
        *(float4*)(Crow)     = make_float4(acc[i][0], acc[i][1], acc[i][2], acc[i][3]);
        *(float4*)(Crow + 4) = make_float4(acc[i][4], acc[i][5], acc[i][6], acc[i][7]);
    }
}

// ---------------------------------------------------------------------------
// RoPE + split
// ---------------------------------------------------------------------------
__global__ __launch_bounds__(256)
void rope_split_kernel()
{
    int idx = blockIdx.x * blockDim.x + threadIdx.x;
    int m = idx >> 11;
    int c = idx & 2047;
    int t = m & (TT-1);
    int d = c & (DD-1);
    int dm = d & 63;

    float ang = (float)t * g_invfreq[dm];
    float sn, cs;
    sincosf(ang, &sn, &cs);

    size_t base = (size_t)m * N_QKV;
    float qv = g_qkv[base + c];
    float kv = g_qkv[base + CC + c];
    float vv = g_qkv[base + 2*CC + c];

    int c2 = (d < 64) ? (c + 64) : (c - 64);
    float sgn = (d < 64) ? -1.f : 1.f;
    float qr = g_qkv[base + c2];
    float kr = g_qkv[base + CC + c2];

    float qo = qv*cs + sgn*qr*sn;
    float ko = kv*cs + sgn*kr*sn;

    int b = m >> 11;
    int h = c >> 7;
    size_t o = (((size_t)(b*HH + h))*TT + t)*DD + d;
    g_q[o] = qo;
    g_k[o] = ko;
    g_v[o] = vv;
}

// ---------------------------------------------------------------------------
// Tiled flash attention.
// Block = 256 threads. BQ=128 queries, BK=64 keys/chunk, D=128.
// S-phase: micro 8q x 4k per thread (16x16 thread grid).
// PV-phase: micro 8q x 8d per thread.
// Smem layouts (pads chosen for conflict-free access):
//   Qt [D][BQ+4]  (d-major, transposed)
//   Kt [D][BK+4]  (d-major, transposed)
//   Vs [BK][D]    (natural)
//   Ps [BQ][BK+4] (row-major)
// ---------------------------------------------------------------------------
#define BQ 128
#define BK 64
#define QPAD (BQ+4)   // 132
#define KPAD (BK+4)   // 68
#define PPAD (BK+4)   // 68
#define ATTN_SMEM ((DD*QPAD + DD*KPAD + BK*DD + BQ*PPAD)*4)

__global__ __launch_bounds__(256, 1)
void attn_tile_kernel()
{
    extern __shared__ float sm[];
    float* Qt = sm;                       // [128][132]
    float* Kt = Qt + DD*QPAD;             // [128][68]
    float* Vs = Kt + DD*KPAD;             // [64][128]
    float* Ps = Vs + BK*DD;               // [128][68]

    const int tid = threadIdx.x;
    const int tx = tid & 15;              // 0..15
    const int ty = tid >> 4;              // 0..15

    const int nqt = TT / BQ;              // 16
    const int qt  = (nqt - 1) - blockIdx.x;   // descending work order
    const int bh  = blockIdx.y;           // 0..31
    const int qt0 = qt * BQ;

    const float* qg = g_q + (size_t)bh*TT*DD;
    const float* kg = g_k + (size_t)bh*TT*DD;
    const float* vg = g_v + (size_t)bh*TT*DD;

    const float scale = 0.08838834764831845f;  // 1/sqrt(128)

    // ---- load Q tile (transposed, scaled): 128x128 = 4096 float4 ----
    #pragma unroll
    for (int e = 0; e < 16; e++) {
        int idx = e*256 + tid;            // 0..4095
        int i  = idx & 127;               // local query
        int d0 = (idx >> 7) * 4;          // 0..124
        float4 v = *(const float4*)(qg + (size_t)(qt0 + i)*DD + d0);
        Qt[(d0+0)*QPAD + i] = v.x * scale;
        Qt[(d0+1)*QPAD + i] = v.y * scale;
        Qt[(d0+2)*QPAD + i] = v.z * scale;
        Qt[(d0+3)*QPAD + i] = v.w * scale;
    }

    float y[8][8];
    float mi[8], li[8];
    #pragma unroll
    for (int ii = 0; ii < 8; ii++) {
        mi[ii] = -1e30f; li[ii] = 0.f;
        #pragma unroll
        for (int jj = 0; jj < 8; jj++) y[ii][jj] = 0.f;
    }

    const int nch = 2*qt + 2;
    for (int c = 0; c < nch; c++) {
        const int j0 = c * BK;

        __syncthreads();   // previous chunk's reads of Kt/Vs done

        // ---- load K chunk transposed: 64x128 = 2048 float4 ----
        #pragma unroll
        for (int e = 0; e < 8; e++) {
            int idx = e*256 + tid;
            int j  = idx & 63;
            int d0 = (idx >> 6) * 4;
            float4 v = *(const float4*)(kg + (size_t)(j0 + j)*DD + d0);
            Kt[(d0+0)*KPAD + j] = v.x;
            Kt[(d0+1)*KPAD + j] = v.y;
            Kt[(d0+2)*KPAD + j] = v.z;
            Kt[(d0+3)*KPAD + j] = v.w;
        }
        // ---- load V chunk natural: coalesced ----
        #pragma unroll
        for (int e = 0; e < 8; e++) {
            int idx = e*256 + tid;
            int r  = idx >> 5;
            int c4 = (idx & 31) * 4;
            *(float4*)&Vs[r*DD + c4] =
                *(const float4*)(vg + (size_t)(j0 + r)*DD + c4);
        }
        __syncthreads();

        // ---- S = Q . K^T : micro 8q x 4k ----
        float s[8][4];
        #pragma unroll
        for (int ii = 0; ii < 8; ii++)
            #pragma unroll
            for (int jj = 0; jj < 4; jj++) s[ii][jj] = 0.f;

        #pragma unroll 4
        for (int d = 0; d < DD; d++) {
            float4 q0 = *(const float4*)&Qt[d*QPAD + ty*8];
            float4 q1 = *(const float4*)&Qt[d*QPAD + ty*8 + 4];
            float4 kv = *(const float4*)&Kt[d*KPAD + tx*4];
            float qf[8] = {q0.x,q0.y,q0.z,q0.w,q1.x,q1.y,q1.z,q1.w};
            float kf[4] = {kv.x,kv.y,kv.z,kv.w};
            #pragma unroll
            for (int ii = 0; ii < 8; ii++)
                #pragma unroll
                for (int jj = 0; jj < 4; jj++)
                    s[ii][jj] = fmaf(qf[ii], kf[jj], s[ii][jj]);
        }

        // ---- causal mask ----
        #pragma unroll
        for (int ii = 0; ii < 8; ii++) {
            int ig = qt0 + ty*8 + ii;
            #pragma unroll
            for (int jj = 0; jj < 4; jj++) {
                int jg = j0 + tx*4 + jj;
                if (jg > ig) s[ii][jj] = -1e30f;
            }
        }

        // ---- online softmax (rows shared by 16 threads w/ same ty) ----
        float corr[8];
        #pragma unroll
        for (int ii = 0; ii < 8; ii++) {
            float m = fmaxf(fmaxf(s[ii][0], s[ii][1]), fmaxf(s[ii][2], s[ii][3]));
            #pragma unroll
            for (int off = 8; off; off >>= 1)
                m = fmaxf(m, __shfl_xor_sync(0xffffffffu, m, off));
            float mnew = fmaxf(mi[ii], m);
            corr[ii] = __expf(mi[ii] - mnew);
            float rs = 0.f;
            #pragma unroll
            for (int jj = 0; jj < 4; jj++) {
                s[ii][jj] = __expf(s[ii][jj] - mnew);
                rs += s[ii][jj];
            }
            #pragma unroll
            for (int off = 8; off; off >>= 1)
                rs += __shfl_xor_sync(0xffffffffu, rs, off);
            li[ii] = li[ii]*corr[ii] + rs;
            mi[ii] = mnew;
            // store P row fragment (float4, conflict-free per phase)
            *(float4*)&Ps[(ty*8+ii)*PPAD + tx*4] =
                make_float4(s[ii][0], s[ii][1], s[ii][2], s[ii][3]);
        }
        __syncthreads();   // Ps visible to all

        // ---- rescale accumulators ----
        #pragma unroll
        for (int ii = 0; ii < 8; ii++) {
            float cr = corr[ii];
            #pragma unroll
            for (int jj = 0; jj < 8; jj++) y[ii][jj] *= cr;
        }

        // ---- Y += P . V : micro 8q x 8d ----
        for (int k0 = 0; k0 < BK; k0 += 4) {
            float4 va[4], vb[4];
            #pragma unroll
            for (int kk = 0; kk < 4; kk++) {
                va[kk] = *(const float4*)&Vs[(k0+kk)*DD + tx*8];
                vb[kk] = *(const float4*)&Vs[(k0+kk)*DD + tx*8 + 4];
            }
            #pragma unroll
            for (int ii = 0; ii < 8; ii++) {
                float4 p4 = *(const float4*)&Ps[(ty*8+ii)*PPAD + k0];
                float pk[4] = {p4.x, p4.y, p4.z, p4.w};
                #pragma unroll
                for (int kk = 0; kk < 4; kk++) {
                    y[ii][0] = fmaf(pk[kk], va[kk].x, y[ii][0]);
                    y[ii][1] = fmaf(pk[kk], va[kk].y, y[ii][1]);
                    y[ii][2] = fmaf(pk[kk], va[kk].z, y[ii][2]);
                    y[ii][3] = fmaf(pk[kk], va[kk].w, y[ii][3]);
                    y[ii][4] = fmaf(pk[kk], vb[kk].x, y[ii][4]);
                    y[ii][5] = fmaf(pk[kk], vb[kk].y, y[ii][5]);
                    y[ii][6] = fmaf(pk[kk], vb[kk].z, y[ii][6]);
                    y[ii][7] = fmaf(pk[kk], vb[kk].w, y[ii][7]);
                }
            }
        }
    }

    // ---- normalize + write to [B,T,C] ----
    const int b = bh >> 4;
    const int h = bh & 15;
    #pragma unroll
    for (int ii = 0; ii < 8; ii++) {
        float inv = 1.f / li[ii];
        int t = qt0 + ty*8 + ii;
        float* yp = g_y + ((size_t)(b*TT + t))*CC + h*DD + tx*8;
        *(float4*)(yp)   = make_float4(y[ii][0]*inv, y[ii][1]*inv, y[ii][2]*inv, y[ii][3]*inv);
        *(float4*)(yp+4) = make_float4(y[ii][4]*inv, y[ii][5]*inv, y[ii][6]*inv, y[ii][7]*inv);
    }
}

// ---------------------------------------------------------------------------
extern "C" void kernel_launch(void* const* d_in, const int* in_sizes, int n_in,
                              void* d_out, int out_size)
{
    const float* x     = (const float*)d_in[0];
    const float* w_qkv = (const float*)d_in[1];
    const float* w_out = (const float*)d_in[2];
    float* out = (float*)d_out;

    float *qkv_ptr, *y_ptr;
    cudaGetSymbolAddress((void**)&qkv_ptr, g_qkv);
    cudaGetSymbolAddress((void**)&y_ptr,  g_y);

    static int smem_set = 0;
    if (!smem_set) {
        cudaFuncSetAttribute(attn_tile_kernel,
                             cudaFuncAttributeMaxDynamicSharedMemorySize,
                             ATTN_SMEM);
        smem_set = 1;
    }

    init_invfreq_kernel<<<1, 64>>>();

    {   // qkv = x @ w_qkv : [4096, 6144]
        dim3 grid(N_QKV/128, MM/128);
        sgemm128_kernel<<<grid, 256>>>(x, w_qkv, qkv_ptr, MM, N_QKV, CC);
    }

    rope_split_kernel<<<(MM*CC)/256, 256>>>();

    {   // causal attention -> g_y [B,T,C]
        dim3 grid(TT/BQ, BB*HH);
        attn_tile_kernel<<<grid, 256, ATTN_SMEM>>>();
    }

    {   // out = y @ w_out : [4096, 2048]
        dim3 grid(CC/128, MM/128);
        sgemm128_kernel<<<grid, 256>>>(y_ptr, w_out, out, MM, CC, CC);
    }
}

// round 4
// speedup vs baseline: 5.5818x; 2.0609x over previous
#include <cuda_runtime.h>
#include <cuda_bf16.h>
#include <cstdint>
#include <math.h>

// Problem constants
#define BB 2
#define TT 2048
#define CC 2048
#define HH 16
#define DD 128
#define MM (BB*TT)          // 4096
#define N_QKV (3*CC)        // 6144

// Scratch (static device globals; no runtime allocation allowed)
__device__ float g_qkv[(size_t)MM * N_QKV];
__device__ float g_q[(size_t)MM * CC];        // [B,H,T,D]
__device__ float g_k[(size_t)MM * CC];
__device__ float g_v[(size_t)MM * CC];
__device__ float g_y[(size_t)MM * CC];        // [B,T,C]
__device__ float g_invfreq[DD/2];

// bf16 split operands
__device__ __nv_bfloat16 g_xh[(size_t)MM * CC];
__device__ __nv_bfloat16 g_xl[(size_t)MM * CC];
__device__ __nv_bfloat16 g_yh[(size_t)MM * CC];
__device__ __nv_bfloat16 g_yl[(size_t)MM * CC];
__device__ __nv_bfloat16 g_wqt_h[(size_t)N_QKV * CC];   // w_qkv^T [N,K]
__device__ __nv_bfloat16 g_wqt_l[(size_t)N_QKV * CC];
__device__ __nv_bfloat16 g_wot_h[(size_t)CC * CC];      // w_out^T [N,K]
__device__ __nv_bfloat16 g_wot_l[(size_t)CC * CC];

// ===========================================================================
// Helpers: baseline-PTX only (sm_80+): cp.async, ldmatrix, mma.sync
// ===========================================================================
__device__ __forceinline__ uint32_t smem_u32(const void* p) {
    uint32_t a;
    asm("{ .reg .u64 t; cvta.to.shared.u64 t, %1; cvt.u32.u64 %0, t; }"
        : "=r"(a) : "l"(p));
    return a;
}
#define CP_ASYNC16(dst, src) \
    asm volatile("cp.async.cg.shared.global [%0], [%1], 16;" :: "r"(dst), "l"(src))
#define CP_COMMIT() asm volatile("cp.async.commit_group;" ::: "memory")
#define CP_WAIT(n)  asm volatile("cp.async.wait_group %0;" :: "n"(n) : "memory")

__device__ __forceinline__ void ldsm4(uint32_t* r, uint32_t addr) {
    asm volatile("ldmatrix.sync.aligned.m8n8.x4.shared.b16 {%0,%1,%2,%3}, [%4];"
        : "=r"(r[0]), "=r"(r[1]), "=r"(r[2]), "=r"(r[3]) : "r"(addr));
}
__device__ __forceinline__ void mma_bf16(float* d, const uint32_t* a, const uint32_t* b) {
    asm volatile("mma.sync.aligned.m16n8k16.row.col.f32.bf16.bf16.f32 "
        "{%0,%1,%2,%3}, {%4,%5,%6,%7}, {%8,%9}, {%0,%1,%2,%3};"
        : "+f"(d[0]), "+f"(d[1]), "+f"(d[2]), "+f"(d[3])
        : "r"(a[0]), "r"(a[1]), "r"(a[2]), "r"(a[3]), "r"(b[0]), "r"(b[1]));
}

// ===========================================================================
__global__ void init_invfreq_kernel() {
    int i = threadIdx.x;
    if (i < DD/2) {
        double e = (double)(2*i) / (double)DD;
        g_invfreq[i] = (float)(1.0 / pow(10000.0, e));
    }
}

// fp32 -> (bf16 hi, bf16 lo)
__global__ __launch_bounds__(256)
void split_convert_kernel(const float* __restrict__ src,
                          __nv_bfloat16* __restrict__ hi,
                          __nv_bfloat16* __restrict__ lo, int n)
{
    int i = blockIdx.x * 256 + threadIdx.x;
    if (i < n) {
        float v = src[i];
        __nv_bfloat16 h = __float2bfloat16(v);
        hi[i] = h;
        lo[i] = __float2bfloat16(v - __bfloat162float(h));
    }
}

// W[K][N] -> Th/Tl[N][K] transposed bf16-split
__global__ __launch_bounds__(256)
void transpose_split_kernel(const float* __restrict__ W,
                            __nv_bfloat16* __restrict__ Th,
                            __nv_bfloat16* __restrict__ Tl, int K, int N)
{
    __shared__ float tile[32][33];
    int n0 = blockIdx.x * 32, k0 = blockIdx.y * 32;
    int tx = threadIdx.x & 31, ty = threadIdx.x >> 5;
    #pragma unroll
    for (int r = 0; r < 4; r++)
        tile[ty + r*8][tx] = W[(size_t)(k0 + ty + r*8)*N + n0 + tx];
    __syncthreads();
    #pragma unroll
    for (int r = 0; r < 4; r++) {
        float v = tile[tx][ty + r*8];
        __nv_bfloat16 h = __float2bfloat16(v);
        size_t o = (size_t)(n0 + ty + r*8)*K + k0 + tx;
        Th[o] = h;
        Tl[o] = __float2bfloat16(v - __bfloat162float(h));
    }
}

// ===========================================================================
// HMMA split-bf16 GEMM: C[M,N] = (Ah+Al)[M,K] . (Bh+Bl)[N,K]^T
// 512 threads, 16 warps (4x4), warp tile 32x32, CTA tile 128x128, KC=64.
// Double-buffered cp.async; 128B smem rows with XOR swizzle for ldmatrix.
// ===========================================================================
#define KC 64
#define TILE_B 16384          // 128 rows x 128 bytes
#define STAGE_B (4*TILE_B)    // Ah, Al, Bh, Bl
#define GH_SMEM (2*STAGE_B)   // 131072

__global__ __launch_bounds__(512, 1)
void gemm_hmma_kernel(const __nv_bfloat16* __restrict__ Ah,
                      const __nv_bfloat16* __restrict__ Al,
                      const __nv_bfloat16* __restrict__ Bh,
                      const __nv_bfloat16* __restrict__ Bl,
                      float* __restrict__ C, int M, int N, int K)
{
    extern __shared__ char sm[];
    const uint32_t sbase = smem_u32(sm);

    const int tid  = threadIdx.x;
    const int wid  = tid >> 5;
    const int lane = tid & 31;
    const int wm = wid >> 2;          // 0..3 (M direction)
    const int wn = wid & 3;           // 0..3 (N direction)
    const int bm = blockIdx.y * 128;
    const int bn = blockIdx.x * 128;

    const __nv_bfloat16* srcs[4] = {
        Ah + (size_t)bm*K, Al + (size_t)bm*K,
        Bh + (size_t)bn*K, Bl + (size_t)bn*K };

    // per-lane ldmatrix row patterns
    const int aRow = wm*32 + (lane & 7) + ((lane >> 3) & 1)*8;   // + mt*16
    const int aCH  = lane >> 4;                                  // col half
    const int bRow = wn*32 + ((lane >> 4) & 1)*8 + (lane & 7);   // + nt2*16
    const int bCH  = (lane >> 3) & 1;

    float acc[2][4][4];
    #pragma unroll
    for (int mt = 0; mt < 2; mt++)
        #pragma unroll
        for (int nt = 0; nt < 4; nt++)
            #pragma unroll
            for (int e = 0; e < 4; e++) acc[mt][nt][e] = 0.f;

    const int nch = K / KC;

    // prologue: stage 0
    {
        uint32_t dstb = sbase;
        #pragma unroll
        for (int t = 0; t < 4; t++) {
            const __nv_bfloat16* sp = srcs[t];
            uint32_t db = dstb + t*TILE_B;
            #pragma unroll
            for (int e = 0; e < 2; e++) {
                int idx = e*512 + tid;
                int row = idx >> 3, u = idx & 7;
                uint32_t d = db + row*128 + ((u ^ (row & 7))*16);
                CP_ASYNC16(d, sp + (size_t)row*K + u*8);
            }
        }
        CP_COMMIT();
    }

    for (int c = 0; c < nch; c++) {
        if (c + 1 < nch) {
            uint32_t dstb = sbase + ((c+1) & 1)*STAGE_B;
            #pragma unroll
            for (int t = 0; t < 4; t++) {
                const __nv_bfloat16* sp = srcs[t] + (c+1)*KC;
                uint32_t db = dstb + t*TILE_B;
                #pragma unroll
                for (int e = 0; e < 2; e++) {
                    int idx = e*512 + tid;
                    int row = idx >> 3, u = idx & 7;
                    uint32_t d = db + row*128 + ((u ^ (row & 7))*16);
                    CP_ASYNC16(d, sp + (size_t)row*K + u*8);
                }
            }
            CP_COMMIT();
            CP_WAIT(1);
        } else {
            CP_WAIT(0);
        }
        __syncthreads();

        const uint32_t stb = sbase + (c & 1)*STAGE_B;

        #pragma unroll
        for (int ks = 0; ks < 4; ks++) {
            uint32_t ah[2][4], al[2][4], bh[2][4], bl[2][4];
            #pragma unroll
            for (int mt = 0; mt < 2; mt++) {
                int r = aRow + mt*16;
                uint32_t off = r*128 + (((ks*2 + aCH) ^ (r & 7))*16);
                ldsm4(ah[mt], stb + 0*TILE_B + off);
                ldsm4(al[mt], stb + 1*TILE_B + off);
            }
            #pragma unroll
            for (int nt2 = 0; nt2 < 2; nt2++) {
                int r = bRow + nt2*16;
                uint32_t off = r*128 + (((ks*2 + bCH) ^ (r & 7))*16);
                ldsm4(bh[nt2], stb + 2*TILE_B + off);
                ldsm4(bl[nt2], stb + 3*TILE_B + off);
            }
            #pragma unroll
            for (int mt = 0; mt < 2; mt++) {
                #pragma unroll
                for (int nt = 0; nt < 4; nt++) {
                    const uint32_t* bhp = &bh[nt >> 1][(nt & 1)*2];
                    const uint32_t* blp = &bl[nt >> 1][(nt & 1)*2];
                    mma_bf16(acc[mt][nt], ah[mt], bhp);   // Ah.Bh
                    mma_bf16(acc[mt][nt], ah[mt], blp);   // Ah.Bl
                    mma_bf16(acc[mt][nt], al[mt], bhp);   // Al.Bh
                }
            }
        }
        __syncthreads();
    }

    // epilogue
    #pragma unroll
    for (int mt = 0; mt < 2; mt++) {
        #pragma unroll
        for (int nt = 0; nt < 4; nt++) {
            int r0 = bm + wm*32 + mt*16 + (lane >> 2);
            int c0 = bn + wn*32 + nt*8 + (lane & 3)*2;
            *(float2*)(C + (size_t)r0*N + c0) =
                make_float2(acc[mt][nt][0], acc[mt][nt][1]);
            *(float2*)(C + (size_t)(r0+8)*N + c0) =
                make_float2(acc[mt][nt][2], acc[mt][nt][3]);
        }
    }
}

// ===========================================================================
// RoPE + split (unchanged)
// ===========================================================================
__global__ __launch_bounds__(256)
void rope_split_kernel()
{
    int idx = blockIdx.x * blockDim.x + threadIdx.x;
    int m = idx >> 11;
    int c = idx & 2047;
    int t = m & (TT-1);
    int d = c & (DD-1);
    int dm = d & 63;

    float ang = (float)t * g_invfreq[dm];
    float sn, cs;
    sincosf(ang, &sn, &cs);

    size_t base = (size_t)m * N_QKV;
    float qv = g_qkv[base + c];
    float kv = g_qkv[base + CC + c];
    float vv = g_qkv[base + 2*CC + c];

    int c2 = (d < 64) ? (c + 64) : (c - 64);
    float sgn = (d < 64) ? -1.f : 1.f;
    float qr = g_qkv[base + c2];
    float kr = g_qkv[base + CC + c2];

    float qo = qv*cs + sgn*qr*sn;
    float ko = kv*cs + sgn*kr*sn;

    int b = m >> 11;
    int h = c >> 7;
    size_t o = (((size_t)(b*HH + h))*TT + t)*DD + d;
    g_q[o] = qo;
    g_k[o] = ko;
    g_v[o] = vv;
}

// ===========================================================================
// Tiled flash attention (unchanged from R2)
// ===========================================================================
#define BQ 128
#define BK 64
#define QPAD (BQ+4)
#define KPAD (BK+4)
#define PPAD (BK+4)
#define ATTN_SMEM ((DD*QPAD + DD*KPAD + BK*DD + BQ*PPAD)*4)

__global__ __launch_bounds__(256, 1)
void attn_tile_kernel()
{
    extern __shared__ float smf[];
    float* Qt = smf;
    float* Kt = Qt + DD*QPAD;
    float* Vs = Kt + DD*KPAD;
    float* Ps = Vs + BK*DD;

    const int tid = threadIdx.x;
    const int tx = tid & 15;
    const int ty = tid >> 4;

    const int nqt = TT / BQ;
    const int qt  = (nqt - 1) - blockIdx.x;
    const int bh  = blockIdx.y;
    const int qt0 = qt * BQ;

    const float* qg = g_q + (size_t)bh*TT*DD;
    const float* kg = g_k + (size_t)bh*TT*DD;
    const float* vg = g_v + (size_t)bh*TT*DD;

    const float scale = 0.08838834764831845f;

    #pragma unroll
    for (int e = 0; e < 16; e++) {
        int idx = e*256 + tid;
        int i  = idx & 127;
        int d0 = (idx >> 7) * 4;
        float4 v = *(const float4*)(qg + (size_t)(qt0 + i)*DD + d0);
        Qt[(d0+0)*QPAD + i] = v.x * scale;
        Qt[(d0+1)*QPAD + i] = v.y * scale;
        Qt[(d0+2)*QPAD + i] = v.z * scale;
        Qt[(d0+3)*QPAD + i] = v.w * scale;
    }

    float y[8][8];
    float mi[8], li[8];
    #pragma unroll
    for (int ii = 0; ii < 8; ii++) {
        mi[ii] = -1e30f; li[ii] = 0.f;
        #pragma unroll
        for (int jj = 0; jj < 8; jj++) y[ii][jj] = 0.f;
    }

    const int nch = 2*qt + 2;
    for (int c = 0; c < nch; c++) {
        const int j0 = c * BK;
        __syncthreads();

        #pragma unroll
        for (int e = 0; e < 8; e++) {
            int idx = e*256 + tid;
            int j  = idx & 63;
            int d0 = (idx >> 6) * 4;
            float4 v = *(const float4*)(kg + (size_t)(j0 + j)*DD + d0);
            Kt[(d0+0)*KPAD + j] = v.x;
            Kt[(d0+1)*KPAD + j] = v.y;
            Kt[(d0+2)*KPAD + j] = v.z;
            Kt[(d0+3)*KPAD + j] = v.w;
        }
        #pragma unroll
        for (int e = 0; e < 8; e++) {
            int idx = e*256 + tid;
            int r  = idx >> 5;
            int c4 = (idx & 31) * 4;
            *(float4*)&Vs[r*DD + c4] =
                *(const float4*)(vg + (size_t)(j0 + r)*DD + c4);
        }
        __syncthreads();

        float s[8][4];
        #pragma unroll
        for (int ii = 0; ii < 8; ii++)
            #pragma unroll
            for (int jj = 0; jj < 4; jj++) s[ii][jj] = 0.f;

        #pragma unroll 4
        for (int d = 0; d < DD; d++) {
            float4 q0 = *(const float4*)&Qt[d*QPAD + ty*8];
            float4 q1 = *(const float4*)&Qt[d*QPAD + ty*8 + 4];
            float4 kv = *(const float4*)&Kt[d*KPAD + tx*4];
            float qf[8] = {q0.x,q0.y,q0.z,q0.w,q1.x,q1.y,q1.z,q1.w};
            float kf[4] = {kv.x,kv.y,kv.z,kv.w};
            #pragma unroll
            for (int ii = 0; ii < 8; ii++)
                #pragma unroll
                for (int jj = 0; jj < 4; jj++)
                    s[ii][jj] = fmaf(qf[ii], kf[jj], s[ii][jj]);
        }

        #pragma unroll
        for (int ii = 0; ii < 8; ii++) {
            int ig = qt0 + ty*8 + ii;
            #pragma unroll
            for (int jj = 0; jj < 4; jj++) {
                int jg = j0 + tx*4 + jj;
                if (jg > ig) s[ii][jj] = -1e30f;
            }
        }

        float corr[8];
        #pragma unroll
        for (int ii = 0; ii < 8; ii++) {
            float m = fmaxf(fmaxf(s[ii][0], s[ii][1]), fmaxf(s[ii][2], s[ii][3]));
            #pragma unroll
            for (int off = 8; off; off >>= 1)
                m = fmaxf(m, __shfl_xor_sync(0xffffffffu, m, off));
            float mnew = fmaxf(mi[ii], m);
            corr[ii] = __expf(mi[ii] - mnew);
            float rs = 0.f;
            #pragma unroll
            for (int jj = 0; jj < 4; jj++) {
                s[ii][jj] = __expf(s[ii][jj] - mnew);
                rs += s[ii][jj];
            }
            #pragma unroll
            for (int off = 8; off; off >>= 1)
                rs += __shfl_xor_sync(0xffffffffu, rs, off);
            li[ii] = li[ii]*corr[ii] + rs;
            mi[ii] = mnew;
            *(float4*)&Ps[(ty*8+ii)*PPAD + tx*4] =
                make_float4(s[ii][0], s[ii][1], s[ii][2], s[ii][3]);
        }
        __syncthreads();

        #pragma unroll
        for (int ii = 0; ii < 8; ii++) {
            float cr = corr[ii];
            #pragma unroll
            for (int jj = 0; jj < 8; jj++) y[ii][jj] *= cr;
        }

        for (int k0 = 0; k0 < BK; k0 += 4) {
            float4 va[4], vb[4];
            #pragma unroll
            for (int kk = 0; kk < 4; kk++) {
                va[kk] = *(const float4*)&Vs[(k0+kk)*DD + tx*8];
                vb[kk] = *(const float4*)&Vs[(k0+kk)*DD + tx*8 + 4];
            }
            #pragma unroll
            for (int ii = 0; ii < 8; ii++) {
                float4 p4 = *(const float4*)&Ps[(ty*8+ii)*PPAD + k0];
                float pk[4] = {p4.x, p4.y, p4.z, p4.w};
                #pragma unroll
                for (int kk = 0; kk < 4; kk++) {
                    y[ii][0] = fmaf(pk[kk], va[kk].x, y[ii][0]);
                    y[ii][1] = fmaf(pk[kk], va[kk].y, y[ii][1]);
                    y[ii][2] = fmaf(pk[kk], va[kk].z, y[ii][2]);
                    y[ii][3] = fmaf(pk[kk], va[kk].w, y[ii][3]);
                    y[ii][4] = fmaf(pk[kk], vb[kk].x, y[ii][4]);
                    y[ii][5] = fmaf(pk[kk], vb[kk].y, y[ii][5]);
                    y[ii][6] = fmaf(pk[kk], vb[kk].z, y[ii][6]);
                    y[ii][7] = fmaf(pk[kk], vb[kk].w, y[ii][7]);
                }
            }
        }
    }

    const int b = bh >> 4;
    const int h = bh & 15;
    #pragma unroll
    for (int ii = 0; ii < 8; ii++) {
        float inv = 1.f / li[ii];
        int t = qt0 + ty*8 + ii;
        float* yp = g_y + ((size_t)(b*TT + t))*CC + h*DD + tx*8;
        *(float4*)(yp)   = make_float4(y[ii][0]*inv, y[ii][1]*inv, y[ii][2]*inv, y[ii][3]*inv);
        *(float4*)(yp+4) = make_float4(y[ii][4]*inv, y[ii][5]*inv, y[ii][6]*inv, y[ii][7]*inv);
    }
}

// ===========================================================================
extern "C" void kernel_launch(void* const* d_in, const int* in_sizes, int n_in,
                              void* d_out, int out_size)
{
    const float* x     = (const float*)d_in[0];
    const float* w_qkv = (const float*)d_in[1];
    const float* w_out = (const float*)d_in[2];
    float* out = (float*)d_out;

    float *qkv_ptr, *y_ptr;
    __nv_bfloat16 *xh, *xl, *yh, *yl, *wqh, *wql, *woh, *wol;
    cudaGetSymbolAddress((void**)&qkv_ptr, g_qkv);
    cudaGetSymbolAddress((void**)&y_ptr,  g_y);
    cudaGetSymbolAddress((void**)&xh, g_xh);
    cudaGetSymbolAddress((void**)&xl, g_xl);
    cudaGetSymbolAddress((void**)&yh, g_yh);
    cudaGetSymbolAddress((void**)&yl, g_yl);
    cudaGetSymbolAddress((void**)&wqh, g_wqt_h);
    cudaGetSymbolAddress((void**)&wql, g_wqt_l);
    cudaGetSymbolAddress((void**)&woh, g_wot_h);
    cudaGetSymbolAddress((void**)&wol, g_wot_l);

    static int attr_set = 0;
    if (!attr_set) {
        cudaFuncSetAttribute(attn_tile_kernel,
                             cudaFuncAttributeMaxDynamicSharedMemorySize, ATTN_SMEM);
        cudaFuncSetAttribute(gemm_hmma_kernel,
                             cudaFuncAttributeMaxDynamicSharedMemorySize, GH_SMEM);
        attr_set = 1;
    }

    init_invfreq_kernel<<<1, 64>>>();

    // split-convert inputs
    split_convert_kernel<<<(MM*CC + 255)/256, 256>>>(x, xh, xl, MM*CC);
    transpose_split_kernel<<<dim3(N_QKV/32, CC/32), 256>>>(w_qkv, wqh, wql, CC, N_QKV);
    transpose_split_kernel<<<dim3(CC/32, CC/32), 256>>>(w_out, woh, wol, CC, CC);

    // qkv = x @ w_qkv  (HMMA tensor cores)
    gemm_hmma_kernel<<<dim3(N_QKV/128, MM/128), 512, GH_SMEM>>>(
        xh, xl, wqh, wql, qkv_ptr, MM, N_QKV, CC);

    rope_split_kernel<<<(MM*CC)/256, 256>>>();

    attn_tile_kernel<<<dim3(TT/BQ, BB*HH), 256, ATTN_SMEM>>>();

    // out = y @ w_out
    split_convert_kernel<<<(MM*CC + 255)/256, 256>>>(y_ptr, yh, yl, MM*CC);
    gemm_hmma_kernel<<<dim3(CC/128, MM/128), 512, GH_SMEM>>>(
        yh, yl, woh, wol, out, MM, CC, CC);
}

// round 5
// speedup vs baseline: 8.7628x; 1.5699x over previous
#include <cuda_runtime.h>
#include <cuda_bf16.h>
#include <cstdint>
#include <math.h>

// Problem constants
#define BB 2
#define TT 2048
#define CC 2048
#define HH 16
#define DD 128
#define MM (BB*TT)          // 4096
#define N_QKV (3*CC)        // 6144

// Scratch (static device globals; no runtime allocation allowed)
__device__ float g_qkv[(size_t)MM * N_QKV];
__device__ float g_invfreq[DD/2];

// bf16 split operands
__device__ __nv_bfloat16 g_xh[(size_t)MM * CC];
__device__ __nv_bfloat16 g_xl[(size_t)MM * CC];
__device__ __nv_bfloat16 g_yh[(size_t)MM * CC];   // attention out [B,T,C] hi
__device__ __nv_bfloat16 g_yl[(size_t)MM * CC];
__device__ __nv_bfloat16 g_wqt_h[(size_t)N_QKV * CC];
__device__ __nv_bfloat16 g_wqt_l[(size_t)N_QKV * CC];
__device__ __nv_bfloat16 g_wot_h[(size_t)CC * CC];
__device__ __nv_bfloat16 g_wot_l[(size_t)CC * CC];
// roped q/k and v in [B,H,T,D], bf16 hi/lo
__device__ __nv_bfloat16 g_qh[(size_t)MM * CC];
__device__ __nv_bfloat16 g_ql[(size_t)MM * CC];
__device__ __nv_bfloat16 g_kh[(size_t)MM * CC];
__device__ __nv_bfloat16 g_kl[(size_t)MM * CC];
__device__ __nv_bfloat16 g_vh[(size_t)MM * CC];
__device__ __nv_bfloat16 g_vl[(size_t)MM * CC];

// ===========================================================================
// Helpers: baseline-PTX only (sm_80+): cp.async, ldmatrix, mma.sync
// ===========================================================================
__device__ __forceinline__ uint32_t smem_u32(const void* p) {
    uint32_t a;
    asm("{ .reg .u64 t; cvta.to.shared.u64 t, %1; cvt.u32.u64 %0, t; }"
        : "=r"(a) : "l"(p));
    return a;
}
#define CP_ASYNC16(dst, src) \
    asm volatile("cp.async.cg.shared.global [%0], [%1], 16;" :: "r"(dst), "l"(src))
#define CP_COMMIT() asm volatile("cp.async.commit_group;" ::: "memory")
#define CP_WAIT(n)  asm volatile("cp.async.wait_group %0;" :: "n"(n) : "memory")

__device__ __forceinline__ void ldsm4(uint32_t* r, uint32_t addr) {
    asm volatile("ldmatrix.sync.aligned.m8n8.x4.shared.b16 {%0,%1,%2,%3}, [%4];"
        : "=r"(r[0]), "=r"(r[1]), "=r"(r[2]), "=r"(r[3]) : "r"(addr));
}
__device__ __forceinline__ void ldsm4t(uint32_t* r, uint32_t addr) {
    asm volatile("ldmatrix.sync.aligned.m8n8.x4.trans.shared.b16 {%0,%1,%2,%3}, [%4];"
        : "=r"(r[0]), "=r"(r[1]), "=r"(r[2]), "=r"(r[3]) : "r"(addr));
}
__device__ __forceinline__ void mma_bf16(float* d, const uint32_t* a, const uint32_t* b) {
    asm volatile("mma.sync.aligned.m16n8k16.row.col.f32.bf16.bf16.f32 "
        "{%0,%1,%2,%3}, {%4,%5,%6,%7}, {%8,%9}, {%0,%1,%2,%3};"
        : "+f"(d[0]), "+f"(d[1]), "+f"(d[2]), "+f"(d[3])
        : "r"(a[0]), "r"(a[1]), "r"(a[2]), "r"(a[3]), "r"(b[0]), "r"(b[1]));
}

// ===========================================================================
__global__ void init_invfreq_kernel() {
    int i = threadIdx.x;
    if (i < DD/2) {
        double e = (double)(2*i) / (double)DD;
        g_invfreq[i] = (float)(1.0 / pow(10000.0, e));
    }
}

__global__ __launch_bounds__(256)
void split_convert_kernel(const float* __restrict__ src,
                          __nv_bfloat16* __restrict__ hi,
                          __nv_bfloat16* __restrict__ lo, int n)
{
    int i = blockIdx.x * 256 + threadIdx.x;
    if (i < n) {
        float v = src[i];
        __nv_bfloat16 h = __float2bfloat16(v);
        hi[i] = h;
        lo[i] = __float2bfloat16(v - __bfloat162float(h));
    }
}

__global__ __launch_bounds__(256)
void transpose_split_kernel(const float* __restrict__ W,
                            __nv_bfloat16* __restrict__ Th,
                            __nv_bfloat16* __restrict__ Tl, int K, int N)
{
    __shared__ float tile[32][33];
    int n0 = blockIdx.x * 32, k0 = blockIdx.y * 32;
    int tx = threadIdx.x & 31, ty = threadIdx.x >> 5;
    #pragma unroll
    for (int r = 0; r < 4; r++)
        tile[ty + r*8][tx] = W[(size_t)(k0 + ty + r*8)*N + n0 + tx];
    __syncthreads();
    #pragma unroll
    for (int r = 0; r < 4; r++) {
        float v = tile[tx][ty + r*8];
        __nv_bfloat16 h = __float2bfloat16(v);
        size_t o = (size_t)(n0 + ty + r*8)*K + k0 + tx;
        Th[o] = h;
        Tl[o] = __float2bfloat16(v - __bfloat162float(h));
    }
}

// ===========================================================================
// HMMA split-bf16 GEMM (unchanged from R4)
// ===========================================================================
#define KC 64
#define TILE_B 16384
#define STAGE_B (4*TILE_B)
#define GH_SMEM (2*STAGE_B)

__global__ __launch_bounds__(512, 1)
void gemm_hmma_kernel(const __nv_bfloat16* __restrict__ Ah,
                      const __nv_bfloat16* __restrict__ Al,
                      const __nv_bfloat16* __restrict__ Bh,
                      const __nv_bfloat16* __restrict__ Bl,
                      float* __restrict__ C, int M, int N, int K)
{
    extern __shared__ char sm[];
    const uint32_t sbase = smem_u32(sm);

    const int tid  = threadIdx.x;
    const int wid  = tid >> 5;
    const int lane = tid & 31;
    const int wm = wid >> 2;
    const int wn = wid & 3;
    const int bm = blockIdx.y * 128;
    const int bn = blockIdx.x * 128;

    const __nv_bfloat16* srcs[4] = {
        Ah + (size_t)bm*K, Al + (size_t)bm*K,
        Bh + (size_t)bn*K, Bl + (size_t)bn*K };

    const int aRow = wm*32 + (lane & 7) + ((lane >> 3) & 1)*8;
    const int aCH  = lane >> 4;
    const int bRow = wn*32 + ((lane >> 4) & 1)*8 + (lane & 7);
    const int bCH  = (lane >> 3) & 1;

    float acc[2][4][4];
    #pragma unroll
    for (int mt = 0; mt < 2; mt++)
        #pragma unroll
        for (int nt = 0; nt < 4; nt++)
            #pragma unroll
            for (int e = 0; e < 4; e++) acc[mt][nt][e] = 0.f;

    const int nch = K / KC;
    {
        uint32_t dstb = sbase;
        #pragma unroll
        for (int t = 0; t < 4; t++) {
            const __nv_bfloat16* sp = srcs[t];
            uint32_t db = dstb + t*TILE_B;
            #pragma unroll
            for (int e = 0; e < 2; e++) {
                int idx = e*512 + tid;
                int row = idx >> 3, u = idx & 7;
                uint32_t d = db + row*128 + ((u ^ (row & 7))*16);
                CP_ASYNC16(d, sp + (size_t)row*K + u*8);
            }
        }
        CP_COMMIT();
    }

    for (int c = 0; c < nch; c++) {
        if (c + 1 < nch) {
            uint32_t dstb = sbase + ((c+1) & 1)*STAGE_B;
            #pragma unroll
            for (int t = 0; t < 4; t++) {
                const __nv_bfloat16* sp = srcs[t] + (c+1)*KC;
                uint32_t db = dstb + t*TILE_B;
                #pragma unroll
                for (int e = 0; e < 2; e++) {
                    int idx = e*512 + tid;
                    int row = idx >> 3, u = idx & 7;
                    uint32_t d = db + row*128 + ((u ^ (row & 7))*16);
                    CP_ASYNC16(d, sp + (size_t)row*K + u*8);
                }
            }
            CP_COMMIT();
            CP_WAIT(1);
        } else {
            CP_WAIT(0);
        }
        __syncthreads();

        const uint32_t stb = sbase + (c & 1)*STAGE_B;

        #pragma unroll
        for (int ks = 0; ks < 4; ks++) {
            uint32_t ah[2][4], al[2][4], bh[2][4], bl[2][4];
            #pragma unroll
            for (int mt = 0; mt < 2; mt++) {
                int r = aRow + mt*16;
                uint32_t off = r*128 + (((ks*2 + aCH) ^ (r & 7))*16);
                ldsm4(ah[mt], stb + 0*TILE_B + off);
                ldsm4(al[mt], stb + 1*TILE_B + off);
            }
            #pragma unroll
            for (int nt2 = 0; nt2 < 2; nt2++) {
                int r = bRow + nt2*16;
                uint32_t off = r*128 + (((ks*2 + bCH) ^ (r & 7))*16);
                ldsm4(bh[nt2], stb + 2*TILE_B + off);
                ldsm4(bl[nt2], stb + 3*TILE_B + off);
            }
            #pragma unroll
            for (int mt = 0; mt < 2; mt++) {
                #pragma unroll
                for (int nt = 0; nt < 4; nt++) {
                    const uint32_t* bhp = &bh[nt >> 1][(nt & 1)*2];
                    const uint32_t* blp = &bl[nt >> 1][(nt & 1)*2];
                    mma_bf16(acc[mt][nt], ah[mt], bhp);
                    mma_bf16(acc[mt][nt], ah[mt], blp);
                    mma_bf16(acc[mt][nt], al[mt], bhp);
                }
            }
        }
        __syncthreads();
    }

    #pragma unroll
    for (int mt = 0; mt < 2; mt++) {
        #pragma unroll
        for (int nt = 0; nt < 4; nt++) {
            int r0 = bm + wm*32 + mt*16 + (lane >> 2);
            int c0 = bn + wn*32 + nt*8 + (lane & 3)*2;
            *(float2*)(C + (size_t)r0*N + c0) =
                make_float2(acc[mt][nt][0], acc[mt][nt][1]);
            *(float2*)(C + (size_t)(r0+8)*N + c0) =
                make_float2(acc[mt][nt][2], acc[mt][nt][3]);
        }
    }
}

// ===========================================================================
// RoPE + split: writes q/k/v as bf16 hi/lo in [B,H,T,D]
// ===========================================================================
__global__ __launch_bounds__(256)
void rope_split_kernel()
{
    int idx = blockIdx.x * blockDim.x + threadIdx.x;
    int m = idx >> 11;
    int c = idx & 2047;
    int t = m & (TT-1);
    int d = c & (DD-1);
    int dm = d & 63;

    float ang = (float)t * g_invfreq[dm];
    float sn, cs;
    sincosf(ang, &sn, &cs);

    size_t base = (size_t)m * N_QKV;
    float qv = g_qkv[base + c];
    float kv = g_qkv[base + CC + c];
    float vv = g_qkv[base + 2*CC + c];

    int c2 = (d < 64) ? (c + 64) : (c - 64);
    float sgn = (d < 64) ? -1.f : 1.f;
    float qr = g_qkv[base + c2];
    float kr = g_qkv[base + CC + c2];

    float qo = qv*cs + sgn*qr*sn;
    float ko = kv*cs + sgn*kr*sn;

    int b = m >> 11;
    int h = c >> 7;
    size_t o = (((size_t)(b*HH + h))*TT + t)*DD + d;

    __nv_bfloat16 qh = __float2bfloat16(qo);
    __nv_bfloat16 kh = __float2bfloat16(ko);
    __nv_bfloat16 vh = __float2bfloat16(vv);
    g_qh[o] = qh; g_ql[o] = __float2bfloat16(qo - __bfloat162float(qh));
    g_kh[o] = kh; g_kl[o] = __float2bfloat16(ko - __bfloat162float(kh));
    g_vh[o] = vh; g_vl[o] = __float2bfloat16(vv - __bfloat162float(vh));
}

// ===========================================================================
// HMMA flash attention. BQ=128, BK=64, D=128, 8 warps x 16 q-rows.
// Smem: Qh/Ql (2 khalf tiles of 128x128B each) then 2 stages of K/V hi/lo.
// ===========================================================================
#define AQ 128
#define AK 64
#define SM_QL 32768
#define SM_STG 65536
#define STG_SZ 65536
#define ATT_SMEM (SM_STG + 2*STG_SZ)   // 196608

__global__ __launch_bounds__(256, 1)
void attn_hmma_kernel()
{
    extern __shared__ char sm[];
    const uint32_t sb = smem_u32(sm);
    const int tid = threadIdx.x, wid = tid >> 5, lane = tid & 31;

    const int qt  = (TT/AQ - 1) - blockIdx.x;    // descending work order
    const int bh  = blockIdx.y;
    const int qt0 = qt * AQ;
    const size_t base = (size_t)bh * TT * DD;
    const __nv_bfloat16 *qhp = g_qh + base, *qlp = g_ql + base;
    const __nv_bfloat16 *khp = g_kh + base, *klp = g_kl + base;
    const __nv_bfloat16 *vhp = g_vh + base, *vlp = g_vl + base;

    // ---- Q tile load (hi+lo), group 0 together with stage 0 ----
    #pragma unroll
    for (int e = 0; e < 16; e++) {
        int idx = e*256 + tid;              // 0..4095
        int arr = idx >> 11;
        int r   = (idx >> 4) & 127;
        int ug  = idx & 15;
        int h2 = ug >> 3, u = ug & 7;
        uint32_t dst = sb + arr*SM_QL + h2*16384 + r*128 + ((u ^ (r & 7))*16);
        const __nv_bfloat16* s = (arr ? qlp : qhp) + (size_t)(qt0 + r)*DD + ug*8;
        CP_ASYNC16(dst, s);
    }

    const int nch = 2*qt + 2;

    // stage loader
    auto load_stage = [&](int buf, int j0) {
        uint32_t stg = sb + SM_STG + buf*STG_SZ;
        #pragma unroll
        for (int e = 0; e < 8; e++) {       // K: hi+lo
            int idx = e*256 + tid;          // 0..2047
            int arr = idx >> 10;
            int r   = (idx >> 4) & 63;
            int ug  = idx & 15;
            int h2 = ug >> 3, u = ug & 7;
            uint32_t dst = stg + arr*16384 + h2*8192 + r*128 + ((u ^ (r & 7))*16);
            const __nv_bfloat16* s = (arr ? klp : khp) + (size_t)(j0 + r)*DD + ug*8;
            CP_ASYNC16(dst, s);
        }
        #pragma unroll
        for (int e = 0; e < 8; e++) {       // V: hi+lo
            int idx = e*256 + tid;
            int arr = idx >> 10;
            int r   = (idx >> 4) & 63;
            int ug  = idx & 15;
            int h2 = ug >> 3, u = ug & 7;
            uint32_t dst = stg + 32768 + arr*16384 + h2*8192 + r*128 + ((u ^ (r & 7))*16);
            const __nv_bfloat16* s = (arr ? vlp : vhp) + (size_t)(j0 + r)*DD + ug*8;
            CP_ASYNC16(dst, s);
        }
    };

    load_stage(0, 0);
    CP_COMMIT();
    if (nch > 1) { load_stage(1, AK); CP_COMMIT(); }

    const int wrow0 = wid * 16;
    const int gq0 = qt0 + wrow0;

    float yac[16][4];
    #pragma unroll
    for (int nf = 0; nf < 16; nf++)
        #pragma unroll
        for (int e = 0; e < 4; e++) yac[nf][e] = 0.f;
    float mi[2] = {-1e30f, -1e30f}, li[2] = {0.f, 0.f};

    const float scale = 0.08838834764831845f;   // 1/sqrt(128)

    for (int c = 0; c < nch; c++) {
        const int j0 = c * AK;
        if (c + 1 < nch) { CP_WAIT(1); } else { CP_WAIT(0); }
        __syncthreads();

        const uint32_t stg = sb + SM_STG + (c & 1)*STG_SZ;

        if (j0 < gq0 + 16) {   // warp has unmasked keys in this chunk
            // ---- S = Q.K^T (split bf16, 3 products) ----
            float sa[8][4];
            #pragma unroll
            for (int nf = 0; nf < 8; nf++)
                #pragma unroll
                for (int e = 0; e < 4; e++) sa[nf][e] = 0.f;

            #pragma unroll
            for (int kh2 = 0; kh2 < 2; kh2++) {
                uint32_t qb  = sb + kh2*16384;
                uint32_t qbl = sb + SM_QL + kh2*16384;
                uint32_t kb  = stg + kh2*8192;
                uint32_t kbl = stg + 16384 + kh2*8192;
                #pragma unroll
                for (int ks = 0; ks < 4; ks++) {
                    int ar = wrow0 + (lane & 7) + ((lane >> 3) & 1)*8;
                    int au = ks*2 + (lane >> 4);
                    uint32_t aoff = ar*128 + ((au ^ (ar & 7))*16);
                    uint32_t Ah[4], Al[4];
                    ldsm4(Ah, qb + aoff);
                    ldsm4(Al, qbl + aoff);
                    int br_ = ((lane >> 4) & 1)*8 + (lane & 7);
                    int bu  = ks*2 + ((lane >> 3) & 1);
                    #pragma unroll
                    for (int nb = 0; nb < 4; nb++) {
                        int r = br_ + nb*16;
                        uint32_t boff = r*128 + ((bu ^ (r & 7))*16);
                        uint32_t Bh4[4], Bl4[4];
                        ldsm4(Bh4, kb + boff);
                        ldsm4(Bl4, kbl + boff);
                        mma_bf16(sa[2*nb],   Ah, Bh4);
                        mma_bf16(sa[2*nb],   Ah, Bl4);
                        mma_bf16(sa[2*nb],   Al, Bh4);
                        mma_bf16(sa[2*nb+1], Ah, Bh4+2);
                        mma_bf16(sa[2*nb+1], Ah, Bl4+2);
                        mma_bf16(sa[2*nb+1], Al, Bh4+2);
                    }
                }
            }

            // scale + causal mask
            #pragma unroll
            for (int nf = 0; nf < 8; nf++)
                #pragma unroll
                for (int e = 0; e < 4; e++) sa[nf][e] *= scale;
            if (j0 + 63 > gq0) {
                #pragma unroll
                for (int nf = 0; nf < 8; nf++)
                    #pragma unroll
                    for (int e = 0; e < 4; e++) {
                        int row = gq0 + (lane >> 2) + (e >> 1)*8;
                        int col = j0 + nf*8 + 2*(lane & 3) + (e & 1);
                        if (col > row) sa[nf][e] = -1e30f;
                    }
            }

            // online softmax (rows owned by quads)
            #pragma unroll
            for (int rh = 0; rh < 2; rh++) {
                float m = -1e30f;
                #pragma unroll
                for (int nf = 0; nf < 8; nf++)
                    m = fmaxf(m, fmaxf(sa[nf][rh*2], sa[nf][rh*2+1]));
                m = fmaxf(m, __shfl_xor_sync(0xffffffffu, m, 1));
                m = fmaxf(m, __shfl_xor_sync(0xffffffffu, m, 2));
                float mnew = fmaxf(mi[rh], m);
                float corr = __expf(mi[rh] - mnew);
                float rs = 0.f;
                #pragma unroll
                for (int nf = 0; nf < 8; nf++) {
                    float p0 = __expf(sa[nf][rh*2]   - mnew);
                    float p1 = __expf(sa[nf][rh*2+1] - mnew);
                    sa[nf][rh*2] = p0; sa[nf][rh*2+1] = p1;
                    rs += p0 + p1;
                }
                rs += __shfl_xor_sync(0xffffffffu, rs, 1);
                rs += __shfl_xor_sync(0xffffffffu, rs, 2);
                li[rh] = li[rh]*corr + rs;
                mi[rh] = mnew;
                #pragma unroll
                for (int nf = 0; nf < 16; nf++) {
                    yac[nf][rh*2]   *= corr;
                    yac[nf][rh*2+1] *= corr;
                }
            }

            // pack P into split-bf16 A fragments (4 k-slices of 16 keys)
            uint32_t pH[4][4], pL[4][4];
            #pragma unroll
            for (int j = 0; j < 4; j++) {
                #pragma unroll
                for (int q = 0; q < 4; q++) {
                    int f = 2*j + (q >> 1);
                    int o = (q & 1)*2;
                    float e0 = sa[f][o], e1 = sa[f][o+1];
                    __nv_bfloat162 hp;
                    hp.x = __float2bfloat16(e0);
                    hp.y = __float2bfloat16(e1);
                    pH[j][q] = *(uint32_t*)&hp;
                    __nv_bfloat162 lp;
                    lp.x = __float2bfloat16(e0 - __bfloat162float(hp.x));
                    lp.y = __float2bfloat16(e1 - __bfloat162float(hp.y));
                    pL[j][q] = *(uint32_t*)&lp;
                }
            }

            // ---- Y += P.V (split bf16, 3 products), V via ldmatrix.trans ----
            const uint32_t vb  = stg + 32768;
            const uint32_t vbl = stg + 49152;
            #pragma unroll
            for (int ks = 0; ks < 4; ks++) {
                #pragma unroll
                for (int db = 0; db < 8; db++) {
                    int m4 = lane >> 3;
                    int j = ks*16 + (m4 & 1)*8 + (lane & 7);
                    int un = (db & 3)*2 + (m4 >> 1);
                    uint32_t off = (db >> 2)*8192 + j*128 + ((un ^ (j & 7))*16);
                    uint32_t Vh4[4], Vl4[4];
                    ldsm4t(Vh4, vb + off);
                    ldsm4t(Vl4, vbl + off);
                    mma_bf16(yac[db*2],   pH[ks], Vh4);
                    mma_bf16(yac[db*2],   pH[ks], Vl4);
                    mma_bf16(yac[db*2],   pL[ks], Vh4);
                    mma_bf16(yac[db*2+1], pH[ks], Vh4+2);
                    mma_bf16(yac[db*2+1], pH[ks], Vl4+2);
                    mma_bf16(yac[db*2+1], pL[ks], Vh4+2);
                }
            }
        }

        __syncthreads();
        if (c + 2 < nch) { load_stage(c & 1, (c+2)*AK); CP_COMMIT(); }
    }

    // ---- epilogue: normalize, split to bf16 hi/lo, write [B,T,C] ----
    const int b = bh >> 4, h = bh & 15;
    #pragma unroll
    for (int rh = 0; rh < 2; rh++) {
        float inv = 1.f / li[rh];
        int t = gq0 + (lane >> 2) + rh*8;
        size_t rowo = ((size_t)(b*TT + t))*CC + h*DD;
        #pragma unroll
        for (int nf = 0; nf < 16; nf++) {
            int col = nf*8 + 2*(lane & 3);
            float y0 = yac[nf][rh*2]*inv, y1 = yac[nf][rh*2+1]*inv;
            __nv_bfloat162 hp, lp;
            hp.x = __float2bfloat16(y0);
            hp.y = __float2bfloat16(y1);
            lp.x = __float2bfloat16(y0 - __bfloat162float(hp.x));
            lp.y = __float2bfloat16(y1 - __bfloat162float(hp.y));
            *(__nv_bfloat162*)(g_yh + rowo + col) = hp;
            *(__nv_bfloat162*)(g_yl + rowo + col) = lp;
        }
    }
}

// ===========================================================================
extern "C" void kernel_launch(void* const* d_in, const int* in_sizes, int n_in,
                              void* d_out, int out_size)
{
    const float* x     = (const float*)d_in[0];
    const float* w_qkv = (const float*)d_in[1];
    const float* w_out = (const float*)d_in[2];
    float* out = (float*)d_out;

    float *qkv_ptr;
    __nv_bfloat16 *xh, *xl, *yh, *yl, *wqh, *wql, *woh, *wol;
    cudaGetSymbolAddress((void**)&qkv_ptr, g_qkv);
    cudaGetSymbolAddress((void**)&xh, g_xh);
    cudaGetSymbolAddress((void**)&xl, g_xl);
    cudaGetSymbolAddress((void**)&yh, g_yh);
    cudaGetSymbolAddress((void**)&yl, g_yl);
    cudaGetSymbolAddress((void**)&wqh, g_wqt_h);
    cudaGetSymbolAddress((void**)&wql, g_wqt_l);
    cudaGetSymbolAddress((void**)&woh, g_wot_h);
    cudaGetSymbolAddress((void**)&wol, g_wot_l);

    static int attr_set = 0;
    if (!attr_set) {
        cudaFuncSetAttribute(gemm_hmma_kernel,
                             cudaFuncAttributeMaxDynamicSharedMemorySize, GH_SMEM);
        cudaFuncSetAttribute(attn_hmma_kernel,
                             cudaFuncAttributeMaxDynamicSharedMemorySize, ATT_SMEM);
        attr_set = 1;
    }

    init_invfreq_kernel<<<1, 64>>>();

    split_convert_kernel<<<(MM*CC + 255)/256, 256>>>(x, xh, xl, MM*CC);
    transpose_split_kernel<<<dim3(N_QKV/32, CC/32), 256>>>(w_qkv, wqh, wql, CC, N_QKV);
    transpose_split_kernel<<<dim3(CC/32, CC/32), 256>>>(w_out, woh, wol, CC, CC);

    // qkv = x @ w_qkv
    gemm_hmma_kernel<<<dim3(N_QKV/128, MM/128), 512, GH_SMEM>>>(
        xh, xl, wqh, wql, qkv_ptr, MM, N_QKV, CC);

    // RoPE + split to bf16 hi/lo [B,H,T,D]
    rope_split_kernel<<<(MM*CC)/256, 256>>>();

    // HMMA flash attention -> yh/yl [B,T,C]
    attn_hmma_kernel<<<dim3(TT/AQ, BB*HH), 256, ATT_SMEM>>>();

    // out = y @ w_out
    gemm_hmma_kernel<<<dim3(CC/128, MM/128), 512, GH_SMEM>>>(
        yh, yl, woh, wol, out, MM, CC, CC);
}

// round 6
// speedup vs baseline: 9.1839x; 1.0481x over previous
#include <cuda_runtime.h>
#include <cuda_bf16.h>
#include <cstdint>
#include <math.h>

// Problem constants
#define BB 2
#define TT 2048
#define CC 2048
#define HH 16
#define DD 128
#define MM (BB*TT)          // 4096
#define N_QKV (3*CC)        // 6144

// Scratch (static device globals; no runtime allocation allowed)
__device__ float g_qkv[(size_t)MM * N_QKV];
__device__ float g_invfreq[DD/2];

// bf16 split operands
__device__ __nv_bfloat16 g_xh[(size_t)MM * CC];
__device__ __nv_bfloat16 g_xl[(size_t)MM * CC];
__device__ __nv_bfloat16 g_yh[(size_t)MM * CC];
__device__ __nv_bfloat16 g_yl[(size_t)MM * CC];
__device__ __nv_bfloat16 g_wqt_h[(size_t)N_QKV * CC];
__device__ __nv_bfloat16 g_wqt_l[(size_t)N_QKV * CC];
__device__ __nv_bfloat16 g_wot_h[(size_t)CC * CC];
__device__ __nv_bfloat16 g_wot_l[(size_t)CC * CC];
__device__ __nv_bfloat16 g_qh[(size_t)MM * CC];
__device__ __nv_bfloat16 g_ql[(size_t)MM * CC];
__device__ __nv_bfloat16 g_kh[(size_t)MM * CC];
__device__ __nv_bfloat16 g_kl[(size_t)MM * CC];
__device__ __nv_bfloat16 g_vh[(size_t)MM * CC];
__device__ __nv_bfloat16 g_vl[(size_t)MM * CC];

// ===========================================================================
__device__ __forceinline__ uint32_t smem_u32(const void* p) {
    uint32_t a;
    asm("{ .reg .u64 t; cvta.to.shared.u64 t, %1; cvt.u32.u64 %0, t; }"
        : "=r"(a) : "l"(p));
    return a;
}
#define CP_ASYNC16(dst, src) \
    asm volatile("cp.async.cg.shared.global [%0], [%1], 16;" :: "r"(dst), "l"(src))
#define CP_COMMIT() asm volatile("cp.async.commit_group;" ::: "memory")
#define CP_WAIT(n)  asm volatile("cp.async.wait_group %0;" :: "n"(n) : "memory")

__device__ __forceinline__ void ldsm4(uint32_t* r, uint32_t addr) {
    asm volatile("ldmatrix.sync.aligned.m8n8.x4.shared.b16 {%0,%1,%2,%3}, [%4];"
        : "=r"(r[0]), "=r"(r[1]), "=r"(r[2]), "=r"(r[3]) : "r"(addr));
}
__device__ __forceinline__ void ldsm4t(uint32_t* r, uint32_t addr) {
    asm volatile("ldmatrix.sync.aligned.m8n8.x4.trans.shared.b16 {%0,%1,%2,%3}, [%4];"
        : "=r"(r[0]), "=r"(r[1]), "=r"(r[2]), "=r"(r[3]) : "r"(addr));
}
__device__ __forceinline__ void mma_bf16(float* d, const uint32_t* a, const uint32_t* b) {
    asm volatile("mma.sync.aligned.m16n8k16.row.col.f32.bf16.bf16.f32 "
        "{%0,%1,%2,%3}, {%4,%5,%6,%7}, {%8,%9}, {%0,%1,%2,%3};"
        : "+f"(d[0]), "+f"(d[1]), "+f"(d[2]), "+f"(d[3])
        : "r"(a[0]), "r"(a[1]), "r"(a[2]), "r"(a[3]), "r"(b[0]), "r"(b[1]));
}

// ===========================================================================
__global__ void init_invfreq_kernel() {
    int i = threadIdx.x;
    if (i < DD/2) {
        double e = (double)(2*i) / (double)DD;
        g_invfreq[i] = (float)(1.0 / pow(10000.0, e));
    }
}

__global__ __launch_bounds__(256)
void split_convert_kernel(const float* __restrict__ src,
                          __nv_bfloat16* __restrict__ hi,
                          __nv_bfloat16* __restrict__ lo, int n)
{
    int i = blockIdx.x * 256 + threadIdx.x;
    if (i < n) {
        float v = src[i];
        __nv_bfloat16 h = __float2bfloat16(v);
        hi[i] = h;
        lo[i] = __float2bfloat16(v - __bfloat162float(h));
    }
}

__global__ __launch_bounds__(256)
void transpose_split_kernel(const float* __restrict__ W,
                            __nv_bfloat16* __restrict__ Th,
                            __nv_bfloat16* __restrict__ Tl, int K, int N)
{
    __shared__ float tile[32][33];
    int n0 = blockIdx.x * 32, k0 = blockIdx.y * 32;
    int tx = threadIdx.x & 31, ty = threadIdx.x >> 5;
    #pragma unroll
    for (int r = 0; r < 4; r++)
        tile[ty + r*8][tx] = W[(size_t)(k0 + ty + r*8)*N + n0 + tx];
    __syncthreads();
    #pragma unroll
    for (int r = 0; r < 4; r++) {
        float v = tile[tx][ty + r*8];
        __nv_bfloat16 h = __float2bfloat16(v);
        size_t o = (size_t)(n0 + ty + r*8)*K + k0 + tx;
        Th[o] = h;
        Tl[o] = __float2bfloat16(v - __bfloat162float(h));
    }
}

// ===========================================================================
// HMMA split-bf16 GEMM: CTA tile 256x128, 512 threads (16 warps 4x4),
// warp tile 64x32, K-chunk 64, double-buffered cp.async.
// Stage layout: Ah(32K) Al(32K) Bh(16K) Bl(16K) = 96KB; 2 stages = 192KB.
// ===========================================================================
#define KC 64
#define A_TB 32768           // 256 rows x 128B
#define B_TB 16384           // 128 rows x 128B
#define STAGE_B (2*A_TB + 2*B_TB)   // 98304
#define GH_SMEM (2*STAGE_B)         // 196608

__global__ __launch_bounds__(512, 1)
void gemm_hmma_kernel(const __nv_bfloat16* __restrict__ Ah,
                      const __nv_bfloat16* __restrict__ Al,
                      const __nv_bfloat16* __restrict__ Bh,
                      const __nv_bfloat16* __restrict__ Bl,
                      float* __restrict__ C, int M, int N, int K)
{
    extern __shared__ char sm[];
    const uint32_t sbase = smem_u32(sm);

    const int tid  = threadIdx.x;
    const int wid  = tid >> 5;
    const int lane = tid & 31;
    const int wm = wid >> 2;          // 0..3 -> 64 rows each
    const int wn = wid & 3;           // 0..3 -> 32 cols each
    const int bm = blockIdx.y * 256;
    const int bn = blockIdx.x * 128;

    const __nv_bfloat16* aSrc[2] = { Ah + (size_t)bm*K, Al + (size_t)bm*K };
    const __nv_bfloat16* bSrc[2] = { Bh + (size_t)bn*K, Bl + (size_t)bn*K };

    const int aRowB = wm*64 + (lane & 7) + ((lane >> 3) & 1)*8;
    const int aCH   = lane >> 4;
    const int bRowB = wn*32 + ((lane >> 4) & 1)*8 + (lane & 7);
    const int bCH   = (lane >> 3) & 1;

    float acc[4][4][4];
    #pragma unroll
    for (int mt = 0; mt < 4; mt++)
        #pragma unroll
        for (int nt = 0; nt < 4; nt++)
            #pragma unroll
            for (int e = 0; e < 4; e++) acc[mt][nt][e] = 0.f;

    auto load_stage = [&](int buf, int kc) {
        uint32_t stg = sbase + buf*STAGE_B;
        #pragma unroll
        for (int t = 0; t < 2; t++) {     // A hi/lo: 2048 units each
            const __nv_bfloat16* sp = aSrc[t] + kc*KC;
            uint32_t db = stg + t*A_TB;
            #pragma unroll
            for (int e = 0; e < 4; e++) {
                int idx = e*512 + tid;
                int row = idx >> 3, u = idx & 7;
                uint32_t d = db + row*128 + ((u ^ (row & 7))*16);
                CP_ASYNC16(d, sp + (size_t)row*K + u*8);
            }
        }
        #pragma unroll
        for (int t = 0; t < 2; t++) {     // B hi/lo: 1024 units each
            const __nv_bfloat16* sp = bSrc[t] + kc*KC;
            uint32_t db = stg + 2*A_TB + t*B_TB;
            #pragma unroll
            for (int e = 0; e < 2; e++) {
                int idx = e*512 + tid;
                int row = idx >> 3, u = idx & 7;
                uint32_t d = db + row*128 + ((u ^ (row & 7))*16);
                CP_ASYNC16(d, sp + (size_t)row*K + u*8);
            }
        }
    };

    const int nch = K / KC;
    load_stage(0, 0);
    CP_COMMIT();

    for (int c = 0; c < nch; c++) {
        if (c + 1 < nch) {
            load_stage((c+1) & 1, c+1);
            CP_COMMIT();
            CP_WAIT(1);
        } else {
            CP_WAIT(0);
        }
        __syncthreads();

        const uint32_t stg = sbase + (c & 1)*STAGE_B;

        #pragma unroll
        for (int ks = 0; ks < 4; ks++) {
            uint32_t ah[4][4], al[4][4], bh[2][4], bl[2][4];
            #pragma unroll
            for (int mt = 0; mt < 4; mt++) {
                int r = aRowB + mt*16;
                uint32_t off = r*128 + (((ks*2 + aCH) ^ (r & 7))*16);
                ldsm4(ah[mt], stg + off);
                ldsm4(al[mt], stg + A_TB + off);
            }
            #pragma unroll
            for (int nt2 = 0; nt2 < 2; nt2++) {
                int r = bRowB + nt2*16;
                uint32_t off = r*128 + (((ks*2 + bCH) ^ (r & 7))*16);
                ldsm4(bh[nt2], stg + 2*A_TB + off);
                ldsm4(bl[nt2], stg + 2*A_TB + B_TB + off);
            }
            #pragma unroll
            for (int mt = 0; mt < 4; mt++) {
                #pragma unroll
                for (int nt = 0; nt < 4; nt++) {
                    const uint32_t* bhp = &bh[nt >> 1][(nt & 1)*2];
                    const uint32_t* blp = &bl[nt >> 1][(nt & 1)*2];
                    mma_bf16(acc[mt][nt], ah[mt], bhp);
                    mma_bf16(acc[mt][nt], ah[mt], blp);
                    mma_bf16(acc[mt][nt], al[mt], bhp);
                }
            }
        }
        __syncthreads();
    }

    #pragma unroll
    for (int mt = 0; mt < 4; mt++) {
        #pragma unroll
        for (int nt = 0; nt < 4; nt++) {
            int r0 = bm + wm*64 + mt*16 + (lane >> 2);
            int c0 = bn + wn*32 + nt*8 + (lane & 3)*2;
            *(float2*)(C + (size_t)r0*N + c0) =
                make_float2(acc[mt][nt][0], acc[mt][nt][1]);
            *(float2*)(C + (size_t)(r0+8)*N + c0) =
                make_float2(acc[mt][nt][2], acc[mt][nt][3]);
        }
    }
}

// ===========================================================================
// RoPE + split (unchanged)
// ===========================================================================
__global__ __launch_bounds__(256)
void rope_split_kernel()
{
    int idx = blockIdx.x * blockDim.x + threadIdx.x;
    int m = idx >> 11;
    int c = idx & 2047;
    int t = m & (TT-1);
    int d = c & (DD-1);
    int dm = d & 63;

    float ang = (float)t * g_invfreq[dm];
    float sn, cs;
    sincosf(ang, &sn, &cs);

    size_t base = (size_t)m * N_QKV;
    float qv = g_qkv[base + c];
    float kv = g_qkv[base + CC + c];
    float vv = g_qkv[base + 2*CC + c];

    int c2 = (d < 64) ? (c + 64) : (c - 64);
    float sgn = (d < 64) ? -1.f : 1.f;
    float qr = g_qkv[base + c2];
    float kr = g_qkv[base + CC + c2];

    float qo = qv*cs + sgn*qr*sn;
    float ko = kv*cs + sgn*kr*sn;

    int b = m >> 11;
    int h = c >> 7;
    size_t o = (((size_t)(b*HH + h))*TT + t)*DD + d;

    __nv_bfloat16 qh = __float2bfloat16(qo);
    __nv_bfloat16 kh = __float2bfloat16(ko);
    __nv_bfloat16 vh = __float2bfloat16(vv);
    g_qh[o] = qh; g_ql[o] = __float2bfloat16(qo - __bfloat162float(qh));
    g_kh[o] = kh; g_kl[o] = __float2bfloat16(ko - __bfloat162float(kh));
    g_vh[o] = vh; g_vl[o] = __float2bfloat16(vv - __bfloat162float(vh));
}

// ===========================================================================
// HMMA flash attention. BQ=128, BK=64, 8 warps x 16 q-rows.
// Warp->row permutation balances causal work across SMSPs:
//   SMSP s gets warps s and s+4; perm makes their row-block indices sum to 7.
// ===========================================================================
#define AQ 128
#define AK 64
#define SM_QL 32768
#define SM_STG 65536
#define STG_SZ 65536
#define ATT_SMEM (SM_STG + 2*STG_SZ)   // 196608

__global__ __launch_bounds__(256, 1)
void attn_hmma_kernel()
{
    extern __shared__ char sm[];
    const uint32_t sb = smem_u32(sm);
    const int tid = threadIdx.x, wid = tid >> 5, lane = tid & 31;

    const int qt  = (TT/AQ - 1) - blockIdx.x;
    const int bh  = blockIdx.y;
    const int qt0 = qt * AQ;
    const size_t base = (size_t)bh * TT * DD;
    const __nv_bfloat16 *qhp = g_qh + base, *qlp = g_ql + base;
    const __nv_bfloat16 *khp = g_kh + base, *klp = g_kl + base;
    const __nv_bfloat16 *vhp = g_vh + base, *vlp = g_vl + base;

    #pragma unroll
    for (int e = 0; e < 16; e++) {
        int idx = e*256 + tid;
        int arr = idx >> 11;
        int r   = (idx >> 4) & 127;
        int ug  = idx & 15;
        int h2 = ug >> 3, u = ug & 7;
        uint32_t dst = sb + arr*SM_QL + h2*16384 + r*128 + ((u ^ (r & 7))*16);
        const __nv_bfloat16* s = (arr ? qlp : qhp) + (size_t)(qt0 + r)*DD + ug*8;
        CP_ASYNC16(dst, s);
    }

    const int nch = 2*qt + 2;

    auto load_stage = [&](int buf, int j0) {
        uint32_t stg = sb + SM_STG + buf*STG_SZ;
        #pragma unroll
        for (int e = 0; e < 8; e++) {
            int idx = e*256 + tid;
            int arr = idx >> 10;
            int r   = (idx >> 4) & 63;
            int ug  = idx & 15;
            int h2 = ug >> 3, u = ug & 7;
            uint32_t dst = stg + arr*16384 + h2*8192 + r*128 + ((u ^ (r & 7))*16);
            const __nv_bfloat16* s = (arr ? klp : khp) + (size_t)(j0 + r)*DD + ug*8;
            CP_ASYNC16(dst, s);
        }
        #pragma unroll
        for (int e = 0; e < 8; e++) {
            int idx = e*256 + tid;
            int arr = idx >> 10;
            int r   = (idx >> 4) & 63;
            int ug  = idx & 15;
            int h2 = ug >> 3, u = ug & 7;
            uint32_t dst = stg + 32768 + arr*16384 + h2*8192 + r*128 + ((u ^ (r & 7))*16);
            const __nv_bfloat16* s = (arr ? vlp : vhp) + (size_t)(j0 + r)*DD + ug*8;
            CP_ASYNC16(dst, s);
        }
    };

    load_stage(0, 0);
    CP_COMMIT();
    if (nch > 1) { load_stage(1, AK); CP_COMMIT(); }

    // SMSP-balancing permutation: warps (s, s+4) row-blocks sum to 7
    const int rowblk = (wid < 4) ? wid : (11 - wid);
    const int wrow0 = rowblk * 16;
    const int gq0 = qt0 + wrow0;

    float yac[16][4];
    #pragma unroll
    for (int nf = 0; nf < 16; nf++)
        #pragma unroll
        for (int e = 0; e < 4; e++) yac[nf][e] = 0.f;
    float mi[2] = {-1e30f, -1e30f}, li[2] = {0.f, 0.f};

    const float scale = 0.08838834764831845f;

    for (int c = 0; c < nch; c++) {
        const int j0 = c * AK;
        if (c + 1 < nch) { CP_WAIT(1); } else { CP_WAIT(0); }
        __syncthreads();

        const uint32_t stg = sb + SM_STG + (c & 1)*STG_SZ;

        if (j0 < gq0 + 16) {
            float sa[8][4];
            #pragma unroll
            for (int nf = 0; nf < 8; nf++)
                #pragma unroll
                for (int e = 0; e < 4; e++) sa[nf][e] = 0.f;

            #pragma unroll
            for (int kh2 = 0; kh2 < 2; kh2++) {
                uint32_t qb  = sb + kh2*16384;
                uint32_t qbl = sb + SM_QL + kh2*16384;
                uint32_t kb  = stg + kh2*8192;
                uint32_t kbl = stg + 16384 + kh2*8192;
                #pragma unroll
                for (int ks = 0; ks < 4; ks++) {
                    int ar = wrow0 + (lane & 7) + ((lane >> 3) & 1)*8;
                    int au = ks*2 + (lane >> 4);
                    uint32_t aoff = ar*128 + ((au ^ (ar & 7))*16);
                    uint32_t Ah[4], Al[4];
                    ldsm4(Ah, qb + aoff);
                    ldsm4(Al, qbl + aoff);
                    int br_ = ((lane >> 4) & 1)*8 + (lane & 7);
                    int bu  = ks*2 + ((lane >> 3) & 1);
                    #pragma unroll
                    for (int nb = 0; nb < 4; nb++) {
                        int r = br_ + nb*16;
                        uint32_t boff = r*128 + ((bu ^ (r & 7))*16);
                        uint32_t Bh4[4], Bl4[4];
                        ldsm4(Bh4, kb + boff);
                        ldsm4(Bl4, kbl + boff);
                        mma_bf16(sa[2*nb],   Ah, Bh4);
                        mma_bf16(sa[2*nb],   Ah, Bl4);
                        mma_bf16(sa[2*nb],   Al, Bh4);
                        mma_bf16(sa[2*nb+1], Ah, Bh4+2);
                        mma_bf16(sa[2*nb+1], Ah, Bl4+2);
                        mma_bf16(sa[2*nb+1], Al, Bh4+2);
                    }
                }
            }

            #pragma unroll
            for (int nf = 0; nf < 8; nf++)
                #pragma unroll
                for (int e = 0; e < 4; e++) sa[nf][e] *= scale;
            if (j0 + 63 > gq0) {
                #pragma unroll
                for (int nf = 0; nf < 8; nf++)
                    #pragma unroll
                    for (int e = 0; e < 4; e++) {
                        int row = gq0 + (lane >> 2) + (e >> 1)*8;
                        int col = j0 + nf*8 + 2*(lane & 3) + (e & 1);
                        if (col > row) sa[nf][e] = -1e30f;
                    }
            }

            #pragma unroll
            for (int rh = 0; rh < 2; rh++) {
                float m = -1e30f;
                #pragma unroll
                for (int nf = 0; nf < 8; nf++)
                    m = fmaxf(m, fmaxf(sa[nf][rh*2], sa[nf][rh*2+1]));
                m = fmaxf(m, __shfl_xor_sync(0xffffffffu, m, 1));
                m = fmaxf(m, __shfl_xor_sync(0xffffffffu, m, 2));
                float mnew = fmaxf(mi[rh], m);
                float corr = __expf(mi[rh] - mnew);
                float rs = 0.f;
                #pragma unroll
                for (int nf = 0; nf < 8; nf++) {
                    float p0 = __expf(sa[nf][rh*2]   - mnew);
                    float p1 = __expf(sa[nf][rh*2+1] - mnew);
                    sa[nf][rh*2] = p0; sa[nf][rh*2+1] = p1;
                    rs += p0 + p1;
                }
                rs += __shfl_xor_sync(0xffffffffu, rs, 1);
                rs += __shfl_xor_sync(0xffffffffu, rs, 2);
                li[rh] = li[rh]*corr + rs;
                mi[rh] = mnew;
                #pragma unroll
                for (int nf = 0; nf < 16; nf++) {
                    yac[nf][rh*2]   *= corr;
                    yac[nf][rh*2+1] *= corr;
                }
            }

            uint32_t pH[4][4], pL[4][4];
            #pragma unroll
            for (int j = 0; j < 4; j++) {
                #pragma unroll
                for (int q = 0; q < 4; q++) {
                    int f = 2*j + (q >> 1);
                    int o = (q & 1)*2;
                    float e0 = sa[f][o], e1 = sa[f][o+1];
                    __nv_bfloat162 hp;
                    hp.x = __float2bfloat16(e0);
                    hp.y = __float2bfloat16(e1);
                    pH[j][q] = *(uint32_t*)&hp;
                    __nv_bfloat162 lp;
                    lp.x = __float2bfloat16(e0 - __bfloat162float(hp.x));
                    lp.y = __float2bfloat16(e1 - __bfloat162float(hp.y));
                    pL[j][q] = *(uint32_t*)&lp;
                }
            }

            const uint32_t vb  = stg + 32768;
            const uint32_t vbl = stg + 49152;
            #pragma unroll
            for (int ks = 0; ks < 4; ks++) {
                #pragma unroll
                for (int db = 0; db < 8; db++) {
                    int m4 = lane >> 3;
                    int j = ks*16 + (m4 & 1)*8 + (lane & 7);
                    int un = (db & 3)*2 + (m4 >> 1);
                    uint32_t off = (db >> 2)*8192 + j*128 + ((un ^ (j & 7))*16);
                    uint32_t Vh4[4], Vl4[4];
                    ldsm4t(Vh4, vb + off);
                    ldsm4t(Vl4, vbl + off);
                    mma_bf16(yac[db*2],   pH[ks], Vh4);
                    mma_bf16(yac[db*2],   pH[ks], Vl4);
                    mma_bf16(yac[db*2],   pL[ks], Vh4);
                    mma_bf16(yac[db*2+1], pH[ks], Vh4+2);
                    mma_bf16(yac[db*2+1], pH[ks], Vl4+2);
                    mma_bf16(yac[db*2+1], pL[ks], Vh4+2);
                }
            }
        }

        __syncthreads();
        if (c + 2 < nch) { load_stage(c & 1, (c+2)*AK); CP_COMMIT(); }
    }

    const int b = bh >> 4, h = bh & 15;
    #pragma unroll
    for (int rh = 0; rh < 2; rh++) {
        float inv = 1.f / li[rh];
        int t = gq0 + (lane >> 2) + rh*8;
        size_t rowo = ((size_t)(b*TT + t))*CC + h*DD;
        #pragma unroll
        for (int nf = 0; nf < 16; nf++) {
            int col = nf*8 + 2*(lane & 3);
            float y0 = yac[nf][rh*2]*inv, y1 = yac[nf][rh*2+1]*inv;
            __nv_bfloat162 hp, lp;
            hp.x = __float2bfloat16(y0);
            hp.y = __float2bfloat16(y1);
            lp.x = __float2bfloat16(y0 - __bfloat162float(hp.x));
            lp.y = __float2bfloat16(y1 - __bfloat162float(hp.y));
            *(__nv_bfloat162*)(g_yh + rowo + col) = hp;
            *(__nv_bfloat162*)(g_yl + rowo + col) = lp;
        }
    }
}

// ===========================================================================
extern "C" void kernel_launch(void* const* d_in, const int* in_sizes, int n_in,
                              void* d_out, int out_size)
{
    const float* x     = (const float*)d_in[0];
    const float* w_qkv = (const float*)d_in[1];
    const float* w_out = (const float*)d_in[2];
    float* out = (float*)d_out;

    float *qkv_ptr;
    __nv_bfloat16 *xh, *xl, *yh, *yl, *wqh, *wql, *woh, *wol;
    cudaGetSymbolAddress((void**)&qkv_ptr, g_qkv);
    cudaGetSymbolAddress((void**)&xh, g_xh);
    cudaGetSymbolAddress((void**)&xl, g_xl);
    cudaGetSymbolAddress((void**)&yh, g_yh);
    cudaGetSymbolAddress((void**)&yl, g_yl);
    cudaGetSymbolAddress((void**)&wqh, g_wqt_h);
    cudaGetSymbolAddress((void**)&wql, g_wqt_l);
    cudaGetSymbolAddress((void**)&woh, g_wot_h);
    cudaGetSymbolAddress((void**)&wol, g_wot_l);

    static int attr_set = 0;
    if (!attr_set) {
        cudaFuncSetAttribute(gemm_hmma_kernel,
                             cudaFuncAttributeMaxDynamicSharedMemorySize, GH_SMEM);
        cudaFuncSetAttribute(attn_hmma_kernel,
                             cudaFuncAttributeMaxDynamicSharedMemorySize, ATT_SMEM);
        attr_set = 1;
    }

    init_invfreq_kernel<<<1, 64>>>();

    split_convert_kernel<<<(MM*CC + 255)/256, 256>>>(x, xh, xl, MM*CC);
    transpose_split_kernel<<<dim3(N_QKV/32, CC/32), 256>>>(w_qkv, wqh, wql, CC, N_QKV);
    transpose_split_kernel<<<dim3(CC/32, CC/32), 256>>>(w_out, woh, wol, CC, CC);

    // qkv = x @ w_qkv
    gemm_hmma_kernel<<<dim3(N_QKV/128, MM/256), 512, GH_SMEM>>>(
        xh, xl, wqh, wql, qkv_ptr, MM, N_QKV, CC);

    rope_split_kernel<<<(MM*CC)/256, 256>>>();

    attn_hmma_kernel<<<dim3(TT/AQ, BB*HH), 256, ATT_SMEM>>>();

    // out = y @ w_out
    gemm_hmma_kernel<<<dim3(CC/128, MM/256), 512, GH_SMEM>>>(
        yh, yl, woh, wol, out, MM, CC, CC);
}

// round 8
// speedup vs baseline: 12.6918x; 1.3820x over previous
#include <cuda_runtime.h>
#include <cuda_fp16.h>
#include <cstdint>
#include <math.h>

// Problem constants
#define BB 2
#define TT 2048
#define CC 2048
#define HH 16
#define DD 128
#define MM (BB*TT)          // 4096
#define N_QKV (3*CC)        // 6144

// Scratch (static device globals; no runtime allocation allowed)
__device__ float g_qkv[(size_t)MM * N_QKV];
__device__ float g_invfreq[DD/2];

// fp16 split operands
__device__ __half g_xh[(size_t)MM * CC];
__device__ __half g_xl[(size_t)MM * CC];
__device__ __half g_yh[(size_t)MM * CC];
__device__ __half g_yl[(size_t)MM * CC];
__device__ __half g_wqt_h[(size_t)N_QKV * CC];   // w_qkv^T [N,K] hi only
__device__ __half g_wot_h[(size_t)CC * CC];      // w_out^T hi only
__device__ __half g_qh[(size_t)MM * CC];         // Q hi only
__device__ __half g_kh[(size_t)MM * CC];
__device__ __half g_kl[(size_t)MM * CC];
__device__ __half g_vh[(size_t)MM * CC];
__device__ __half g_vl[(size_t)MM * CC];

// ===========================================================================
__device__ __forceinline__ uint32_t smem_u32(const void* p) {
    uint32_t a;
    asm("{ .reg .u64 t; cvta.to.shared.u64 t, %1; cvt.u32.u64 %0, t; }"
        : "=r"(a) : "l"(p));
    return a;
}
#define CP_ASYNC16(dst, src) \
    asm volatile("cp.async.cg.shared.global [%0], [%1], 16;" :: "r"(dst), "l"(src))
#define CP_COMMIT() asm volatile("cp.async.commit_group;" ::: "memory")
#define CP_WAIT(n)  asm volatile("cp.async.wait_group %0;" :: "n"(n) : "memory")

__device__ __forceinline__ void ldsm4(uint32_t* r, uint32_t addr) {
    asm volatile("ldmatrix.sync.aligned.m8n8.x4.shared.b16 {%0,%1,%2,%3}, [%4];"
        : "=r"(r[0]), "=r"(r[1]), "=r"(r[2]), "=r"(r[3]) : "r"(addr));
}
__device__ __forceinline__ void ldsm4t(uint32_t* r, uint32_t addr) {
    asm volatile("ldmatrix.sync.aligned.m8n8.x4.trans.shared.b16 {%0,%1,%2,%3}, [%4];"
        : "=r"(r[0]), "=r"(r[1]), "=r"(r[2]), "=r"(r[3]) : "r"(addr));
}
__device__ __forceinline__ void mma_f16(float* d, const uint32_t* a, const uint32_t* b) {
    asm volatile("mma.sync.aligned.m16n8k16.row.col.f32.f16.f16.f32 "
        "{%0,%1,%2,%3}, {%4,%5,%6,%7}, {%8,%9}, {%0,%1,%2,%3};"
        : "+f"(d[0]), "+f"(d[1]), "+f"(d[2]), "+f"(d[3])
        : "r"(a[0]), "r"(a[1]), "r"(a[2]), "r"(a[3]), "r"(b[0]), "r"(b[1]));
}

// ===========================================================================
__global__ void init_invfreq_kernel() {
    int i = threadIdx.x;
    if (i < DD/2) {
        double e = (double)(2*i) / (double)DD;
        g_invfreq[i] = (float)(1.0 / pow(10000.0, e));
    }
}

// fp32 -> (fp16 hi, fp16 lo)
__global__ __launch_bounds__(256)
void split_convert_kernel(const float* __restrict__ src,
                          __half* __restrict__ hi,
                          __half* __restrict__ lo, int n)
{
    int i = blockIdx.x * 256 + threadIdx.x;
    if (i < n) {
        float v = src[i];
        __half h = __float2half(v);
        hi[i] = h;
        lo[i] = __float2half(v - __half2float(h));
    }
}

// W[K][N] -> Th[N][K] transposed fp16 hi only
__global__ __launch_bounds__(256)
void transpose_split_kernel(const float* __restrict__ W,
                            __half* __restrict__ Th, int K, int N)
{
    __shared__ float tile[32][33];
    int n0 = blockIdx.x * 32, k0 = blockIdx.y * 32;
    int tx = threadIdx.x & 31, ty = threadIdx.x >> 5;
    #pragma unroll
    for (int r = 0; r < 4; r++)
        tile[ty + r*8][tx] = W[(size_t)(k0 + ty + r*8)*N + n0 + tx];
    __syncthreads();
    #pragma unroll
    for (int r = 0; r < 4; r++) {
        float v = tile[tx][ty + r*8];
        Th[(size_t)(n0 + ty + r*8)*K + k0 + tx] = __float2half(v);
    }
}

// ===========================================================================
// HMMA fp16 2-product GEMM: C = (Ah+Al)[M,K] . Bh[N,K]^T
// CTA tile 128x128, 256 threads (8 warps 2x4), warp tile 64x32, KC=64.
// Stage: Ah(16K) Al(16K) Bh(16K) = 48KB; double-buffered = 96KB.
// ===========================================================================
#define KC 64
#define GT_B 16384
#define STAGE_B (3*GT_B)
#define GH_SMEM (2*STAGE_B)   // 98304

__global__ __launch_bounds__(256, 1)
void gemm_hmma_kernel(const __half* __restrict__ Ah,
                      const __half* __restrict__ Al,
                      const __half* __restrict__ Bh,
                      float* __restrict__ C, int M, int N, int K)
{
    extern __shared__ char sm[];
    const uint32_t sbase = smem_u32(sm);

    const int tid  = threadIdx.x;
    const int wid  = tid >> 5;
    const int lane = tid & 31;
    const int wm = wid >> 2;          // 0..1 -> 64 rows
    const int wn = wid & 3;           // 0..3 -> 32 cols
    const int bm = blockIdx.y * 128;
    const int bn = blockIdx.x * 128;

    const __half* srcs[3] = { Ah + (size_t)bm*K, Al + (size_t)bm*K,
                              Bh + (size_t)bn*K };

    const int aRowB = wm*64 + (lane & 7) + ((lane >> 3) & 1)*8;
    const int aCH   = lane >> 4;
    const int bRowB = wn*32 + ((lane >> 4) & 1)*8 + (lane & 7);
    const int bCH   = (lane >> 3) & 1;

    float acc[4][4][4];
    #pragma unroll
    for (int mt = 0; mt < 4; mt++)
        #pragma unroll
        for (int nt = 0; nt < 4; nt++)
            #pragma unroll
            for (int e = 0; e < 4; e++) acc[mt][nt][e] = 0.f;

    auto load_stage = [&](int buf, int kc) {
        uint32_t stg = sbase + buf*STAGE_B;
        #pragma unroll
        for (int t = 0; t < 3; t++) {
            const __half* sp = srcs[t] + kc*KC;
            uint32_t db = stg + t*GT_B;
            #pragma unroll
            for (int e = 0; e < 4; e++) {
                int idx = e*256 + tid;            // 0..1023
                int row = idx >> 3, u = idx & 7;
                uint32_t d = db + row*128 + ((u ^ (row & 7))*16);
                CP_ASYNC16(d, sp + (size_t)row*K + u*8);
            }
        }
    };

    const int nch = K / KC;
    load_stage(0, 0);
    CP_COMMIT();

    for (int c = 0; c < nch; c++) {
        if (c + 1 < nch) {
            load_stage((c+1) & 1, c+1);
            CP_COMMIT();
            CP_WAIT(1);
        } else {
            CP_WAIT(0);
        }
        __syncthreads();

        const uint32_t stg = sbase + (c & 1)*STAGE_B;

        #pragma unroll
        for (int ks = 0; ks < 4; ks++) {
            uint32_t ah[4][4], al[4][4], bh[2][4];
            #pragma unroll
            for (int mt = 0; mt < 4; mt++) {
                int r = aRowB + mt*16;
                uint32_t off = r*128 + (((ks*2 + aCH) ^ (r & 7))*16);
                ldsm4(ah[mt], stg + off);
                ldsm4(al[mt], stg + GT_B + off);
            }
            #pragma unroll
            for (int nt2 = 0; nt2 < 2; nt2++) {
                int r = bRowB + nt2*16;
                uint32_t off = r*128 + (((ks*2 + bCH) ^ (r & 7))*16);
                ldsm4(bh[nt2], stg + 2*GT_B + off);
            }
            #pragma unroll
            for (int mt = 0; mt < 4; mt++) {
                #pragma unroll
                for (int nt = 0; nt < 4; nt++) {
                    const uint32_t* bhp = &bh[nt >> 1][(nt & 1)*2];
                    mma_f16(acc[mt][nt], ah[mt], bhp);
                    mma_f16(acc[mt][nt], al[mt], bhp);
                }
            }
        }
        __syncthreads();
    }

    #pragma unroll
    for (int mt = 0; mt < 4; mt++) {
        #pragma unroll
        for (int nt = 0; nt < 4; nt++) {
            int r0 = bm + wm*64 + mt*16 + (lane >> 2);
            int c0 = bn + wn*32 + nt*8 + (lane & 3)*2;
            *(float2*)(C + (size_t)r0*N + c0) =
                make_float2(acc[mt][nt][0], acc[mt][nt][1]);
            *(float2*)(C + (size_t)(r0+8)*N + c0) =
                make_float2(acc[mt][nt][2], acc[mt][nt][3]);
        }
    }
}

// ===========================================================================
// RoPE + split: q hi only; k, v hi+lo, all [B,H,T,D] fp16
// ===========================================================================
__global__ __launch_bounds__(256)
void rope_split_kernel()
{
    int idx = blockIdx.x * blockDim.x + threadIdx.x;
    int m = idx >> 11;
    int c = idx & 2047;
    int t = m & (TT-1);
    int d = c & (DD-1);
    int dm = d & 63;

    float ang = (float)t * g_invfreq[dm];
    float sn, cs;
    sincosf(ang, &sn, &cs);

    size_t base = (size_t)m * N_QKV;
    float qv = g_qkv[base + c];
    float kv = g_qkv[base + CC + c];
    float vv = g_qkv[base + 2*CC + c];

    int c2 = (d < 64) ? (c + 64) : (c - 64);
    float sgn = (d < 64) ? -1.f : 1.f;
    float qr = g_qkv[base + c2];
    float kr = g_qkv[base + CC + c2];

    float qo = qv*cs + sgn*qr*sn;
    float ko = kv*cs + sgn*kr*sn;

    int b = m >> 11;
    int h = c >> 7;
    size_t o = (((size_t)(b*HH + h))*TT + t)*DD + d;

    g_qh[o] = __float2half(qo);
    __half kh = __float2half(ko);
    __half vh = __float2half(vv);
    g_kh[o] = kh; g_kl[o] = __float2half(ko - __half2float(kh));
    g_vh[o] = vh; g_vl[o] = __float2half(vv - __half2float(vh));
}

// ===========================================================================
// HMMA fp16 flash attention. BQ=128, BK=64, 8 warps x 16 q-rows.
// Q single fp16; K = Kh+Kl; P single fp16; V = Vh+Vl. 2 products per phase.
// ===========================================================================
#define AQ 128
#define AK 64
#define SM_Q 32768
#define STG_SZ 65536
#define ATT_SMEM (SM_Q + 2*STG_SZ)   // 163840

__global__ __launch_bounds__(256, 1)
void attn_hmma_kernel()
{
    extern __shared__ char sm[];
    const uint32_t sb = smem_u32(sm);
    const int tid = threadIdx.x, wid = tid >> 5, lane = tid & 31;

    const int qt  = (TT/AQ - 1) - blockIdx.x;
    const int bh  = blockIdx.y;
    const int qt0 = qt * AQ;
    const size_t base = (size_t)bh * TT * DD;
    const __half *qhp = g_qh + base;
    const __half *khp = g_kh + base, *klp = g_kl + base;
    const __half *vhp = g_vh + base, *vlp = g_vl + base;

    // Q tile (hi only): 128 rows x 16 units = 2048 cp16
    #pragma unroll
    for (int e = 0; e < 8; e++) {
        int idx = e*256 + tid;              // 0..2047
        int r   = (idx >> 4) & 127;
        int ug  = idx & 15;
        int h2 = ug >> 3, u = ug & 7;
        uint32_t dst = sb + h2*16384 + r*128 + ((u ^ (r & 7))*16);
        CP_ASYNC16(dst, qhp + (size_t)(qt0 + r)*DD + ug*8);
    }

    const int nch = 2*qt + 2;

    auto load_stage = [&](int buf, int j0) {
        uint32_t stg = sb + SM_Q + buf*STG_SZ;
        #pragma unroll
        for (int e = 0; e < 8; e++) {       // K hi+lo
            int idx = e*256 + tid;
            int arr = idx >> 10;
            int r   = (idx >> 4) & 63;
            int ug  = idx & 15;
            int h2 = ug >> 3, u = ug & 7;
            uint32_t dst = stg + arr*16384 + h2*8192 + r*128 + ((u ^ (r & 7))*16);
            const __half* s = (arr ? klp : khp) + (size_t)(j0 + r)*DD + ug*8;
            CP_ASYNC16(dst, s);
        }
        #pragma unroll
        for (int e = 0; e < 8; e++) {       // V hi+lo
            int idx = e*256 + tid;
            int arr = idx >> 10;
            int r   = (idx >> 4) & 63;
            int ug  = idx & 15;
            int h2 = ug >> 3, u = ug & 7;
            uint32_t dst = stg + 32768 + arr*16384 + h2*8192 + r*128 + ((u ^ (r & 7))*16);
            const __half* s = (arr ? vlp : vhp) + (size_t)(j0 + r)*DD + ug*8;
            CP_ASYNC16(dst, s);
        }
    };

    load_stage(0, 0);
    CP_COMMIT();
    if (nch > 1) { load_stage(1, AK); CP_COMMIT(); }

    // SMSP-balancing permutation: warps (s, s+4) row-blocks sum to 7
    const int rowblk = (wid < 4) ? wid : (11 - wid);
    const int wrow0 = rowblk * 16;
    const int gq0 = qt0 + wrow0;

    float yac[16][4];
    #pragma unroll
    for (int nf = 0; nf < 16; nf++)
        #pragma unroll
        for (int e = 0; e < 4; e++) yac[nf][e] = 0.f;
    float mi[2] = {-1e30f, -1e30f}, li[2] = {0.f, 0.f};

    const float scale = 0.08838834764831845f;

    for (int c = 0; c < nch; c++) {
        const int j0 = c * AK;
        if (c + 1 < nch) { CP_WAIT(1); } else { CP_WAIT(0); }
        __syncthreads();

        const uint32_t stg = sb + SM_Q + (c & 1)*STG_SZ;

        if (j0 < gq0 + 16) {
            float sa[8][4];
            #pragma unroll
            for (int nf = 0; nf < 8; nf++)
                #pragma unroll
                for (int e = 0; e < 4; e++) sa[nf][e] = 0.f;

            #pragma unroll
            for (int kh2 = 0; kh2 < 2; kh2++) {
                uint32_t qb  = sb + kh2*16384;
                uint32_t kb  = stg + kh2*8192;
                uint32_t kbl = stg + 16384 + kh2*8192;
                #pragma unroll
                for (int ks = 0; ks < 4; ks++) {
                    int ar = wrow0 + (lane & 7) + ((lane >> 3) & 1)*8;
                    int au = ks*2 + (lane >> 4);
                    uint32_t aoff = ar*128 + ((au ^ (ar & 7))*16);
                    uint32_t Qh4[4];
                    ldsm4(Qh4, qb + aoff);
                    int br_ = ((lane >> 4) & 1)*8 + (lane & 7);
                    int bu  = ks*2 + ((lane >> 3) & 1);
                    #pragma unroll
                    for (int nb = 0; nb < 4; nb++) {
                        int r = br_ + nb*16;
                        uint32_t boff = r*128 + ((bu ^ (r & 7))*16);
                        uint32_t Kh4[4], Kl4[4];
                        ldsm4(Kh4, kb + boff);
                        ldsm4(Kl4, kbl + boff);
                        mma_f16(sa[2*nb],   Qh4, Kh4);
                        mma_f16(sa[2*nb],   Qh4, Kl4);
                        mma_f16(sa[2*nb+1], Qh4, Kh4+2);
                        mma_f16(sa[2*nb+1], Qh4, Kl4+2);
                    }
                }
            }

            #pragma unroll
            for (int nf = 0; nf < 8; nf++)
                #pragma unroll
                for (int e = 0; e < 4; e++) sa[nf][e] *= scale;
            if (j0 + 63 > gq0) {
                #pragma unroll
                for (int nf = 0; nf < 8; nf++)
                    #pragma unroll
                    for (int e = 0; e < 4; e++) {
                        int row = gq0 + (lane >> 2) + (e >> 1)*8;
                        int col = j0 + nf*8 + 2*(lane & 3) + (e & 1);
                        if (col > row) sa[nf][e] = -1e30f;
                    }
            }

            #pragma unroll
            for (int rh = 0; rh < 2; rh++) {
                float m = -1e30f;
                #pragma unroll
                for (int nf = 0; nf < 8; nf++)
                    m = fmaxf(m, fmaxf(sa[nf][rh*2], sa[nf][rh*2+1]));
                m = fmaxf(m, __shfl_xor_sync(0xffffffffu, m, 1));
                m = fmaxf(m, __shfl_xor_sync(0xffffffffu, m, 2));
                float mnew = fmaxf(mi[rh], m);
                float corr = __expf(mi[rh] - mnew);
                float rs = 0.f;
                #pragma unroll
                for (int nf = 0; nf < 8; nf++) {
                    float p0 = __expf(sa[nf][rh*2]   - mnew);
                    float p1 = __expf(sa[nf][rh*2+1] - mnew);
                    sa[nf][rh*2] = p0; sa[nf][rh*2+1] = p1;
                    rs += p0 + p1;
                }
                rs += __shfl_xor_sync(0xffffffffu, rs, 1);
                rs += __shfl_xor_sync(0xffffffffu, rs, 2);
                li[rh] = li[rh]*corr + rs;
                mi[rh] = mnew;
                #pragma unroll
                for (int nf = 0; nf < 16; nf++) {
                    yac[nf][rh*2]   *= corr;
                    yac[nf][rh*2+1] *= corr;
                }
            }

            // pack P (single fp16)
            uint32_t pH[4][4];
            #pragma unroll
            for (int j = 0; j < 4; j++) {
                #pragma unroll
                for (int q = 0; q < 4; q++) {
                    int f = 2*j + (q >> 1);
                    int o = (q & 1)*2;
                    __half2 hp;
                    hp.x = __float2half(sa[f][o]);
                    hp.y = __float2half(sa[f][o+1]);
                    pH[j][q] = *(uint32_t*)&hp;
                }
            }

            // Y += P.(Vh + Vl)
            const uint32_t vb  = stg + 32768;
            const uint32_t vbl = stg + 49152;
            #pragma unroll
            for (int ks = 0; ks < 4; ks++) {
                #pragma unroll
                for (int db = 0; db < 8; db++) {
                    int m4 = lane >> 3;
                    int j = ks*16 + (m4 & 1)*8 + (lane & 7);
                    int un = (db & 3)*2 + (m4 >> 1);
                    uint32_t off = (db >> 2)*8192 + j*128 + ((un ^ (j & 7))*16);
                    uint32_t Vh4[4], Vl4[4];
                    ldsm4t(Vh4, vb + off);
                    ldsm4t(Vl4, vbl + off);
                    mma_f16(yac[db*2],   pH[ks], Vh4);
                    mma_f16(yac[db*2],   pH[ks], Vl4);
                    mma_f16(yac[db*2+1], pH[ks], Vh4+2);
                    mma_f16(yac[db*2+1], pH[ks], Vl4+2);
                }
            }
        }

        __syncthreads();
        if (c + 2 < nch) { load_stage(c & 1, (c+2)*AK); CP_COMMIT(); }
    }

    // epilogue: normalize, split fp16 hi/lo, write [B,T,C]
    const int b = bh >> 4, h = bh & 15;
    #pragma unroll
    for (int rh = 0; rh < 2; rh++) {
        float inv = 1.f / li[rh];
        int t = gq0 + (lane >> 2) + rh*8;
        size_t rowo = ((size_t)(b*TT + t))*CC + h*DD;
        #pragma unroll
        for (int nf = 0; nf < 16; nf++) {
            int col = nf*8 + 2*(lane & 3);
            float y0 = yac[nf][rh*2]*inv, y1 = yac[nf][rh*2+1]*inv;
            __half2 hp, lp;
            hp.x = __float2half(y0);
            hp.y = __float2half(y1);
            lp.x = __float2half(y0 - __half2float(hp.x));
            lp.y = __float2half(y1 - __half2float(hp.y));
            *(__half2*)(g_yh + rowo + col) = hp;
            *(__half2*)(g_yl + rowo + col) = lp;
        }
    }
}

// ===========================================================================
extern "C" void kernel_launch(void* const* d_in, const int* in_sizes, int n_in,
                              void* d_out, int out_size)
{
    const float* x     = (const float*)d_in[0];
    const float* w_qkv = (const float*)d_in[1];
    const float* w_out = (const float*)d_in[2];
    float* out = (float*)d_out;

    float *qkv_ptr;
    __half *xh, *xl, *yh, *yl, *wqh, *woh;
    cudaGetSymbolAddress((void**)&qkv_ptr, g_qkv);
    cudaGetSymbolAddress((void**)&xh, g_xh);
    cudaGetSymbolAddress((void**)&xl, g_xl);
    cudaGetSymbolAddress((void**)&yh, g_yh);
    cudaGetSymbolAddress((void**)&yl, g_yl);
    cudaGetSymbolAddress((void**)&wqh, g_wqt_h);
    cudaGetSymbolAddress((void**)&woh, g_wot_h);

    static int attr_set = 0;
    if (!attr_set) {
        cudaFuncSetAttribute(gemm_hmma_kernel,
                             cudaFuncAttributeMaxDynamicSharedMemorySize, GH_SMEM);
        cudaFuncSetAttribute(attn_hmma_kernel,
                             cudaFuncAttributeMaxDynamicSharedMemorySize, ATT_SMEM);
        attr_set = 1;
    }

    init_invfreq_kernel<<<1, 64>>>();

    split_convert_kernel<<<(MM*CC + 255)/256, 256>>>(x, xh, xl, MM*CC);
    transpose_split_kernel<<<dim3(N_QKV/32, CC/32), 256>>>(w_qkv, wqh, CC, N_QKV);
    transpose_split_kernel<<<dim3(CC/32, CC/32), 256>>>(w_out, woh, CC, CC);

    // qkv = x @ w_qkv
    gemm_hmma_kernel<<<dim3(N_QKV/128, MM/128), 256, GH_SMEM>>>(
        xh, xl, wqh, qkv_ptr, MM, N_QKV, CC);

    rope_split_kernel<<<(MM*CC)/256, 256>>>();

    attn_hmma_kernel<<<dim3(TT/AQ, BB*HH), 256, ATT_SMEM>>>();

    // out = y @ w_out
    gemm_hmma_kernel<<<dim3(CC/128, MM/128), 256, GH_SMEM>>>(
        yh, yl, woh, out, MM, CC, CC);
}